// round 1
// baseline (speedup 1.0000x reference)
#include <cuda_runtime.h>
#include <cuda_bf16.h>
#include <cstdint>

// Problem constants
#define B_    8
#define C_    512
#define N_    1024     // W*H = 32*32
#define HEADS_ 8
#define DH_   64
#define WSP_  32       // spatial W
#define HSP_  32       // spatial H

// ---------------------------------------------------------------------------
// Scratch (static device globals — no allocation in kernel_launch)
// ---------------------------------------------------------------------------
__device__ float g_q[B_ * C_ * N_];            // [b][h*64+d][n]  (16.8 MB)
__device__ float g_k[B_ * C_ * N_];
__device__ float g_v[B_ * C_ * N_];
__device__ float g_pos[HEADS_ * DH_ * N_];     // [h][d][n]       (2 MB)
__device__ float g_att[(size_t)B_ * HEADS_ * N_ * N_];  // [bh][i][j] (256 MB)

// ---------------------------------------------------------------------------
// Kernel 0: pos[h][d][n] = rel_h[h][d][hh] + rel_w[h][d][ww],  n = ww*32 + hh
// ---------------------------------------------------------------------------
__global__ void pos_kernel(const float* __restrict__ rel_h,
                           const float* __restrict__ rel_w) {
    int idx = blockIdx.x * blockDim.x + threadIdx.x;
    if (idx >= HEADS_ * DH_ * N_) return;
    int n = idx & (N_ - 1);
    int d = (idx >> 10) & (DH_ - 1);
    int h = idx >> 16;
    int ww = n >> 5;     // n = ww*HSP_ + hh
    int hh = n & 31;
    // rel_h: (1, HEADS, DH, 1, HSP_)  -> [h][d][hh]
    // rel_w: (1, HEADS, DH, WSP_, 1)  -> [h][d][ww]
    g_pos[idx] = rel_h[(h * DH_ + d) * HSP_ + hh] +
                 rel_w[(h * DH_ + d) * WSP_ + ww];
}

// ---------------------------------------------------------------------------
// Kernel 1: projections  Y_b = W @ X_b + bias   (per batch, per proj)
//   X: [B][C][N] row-major (N contiguous), W: [C][C] row-major, Y same as X.
//   128x128 tile, K-step 8, 256 threads, 8x8 microtile.
//   grid = (N/128=8, C/128=4, 3*B=24)
// ---------------------------------------------------------------------------
__global__ __launch_bounds__(256) void proj_kernel(
    const float* __restrict__ x, const float* __restrict__ dtn,
    const float* __restrict__ Wq, const float* __restrict__ bq,
    const float* __restrict__ Wk, const float* __restrict__ bk,
    const float* __restrict__ Wv, const float* __restrict__ bv) {
    int z = blockIdx.z;
    int proj = z >> 3, b = z & 7;
    const float* X; const float* W; const float* bias; float* Y;
    if (proj == 0)      { X = x;   W = Wq; bias = bq; Y = g_q; }
    else if (proj == 1) { X = dtn; W = Wk; bias = bk; Y = g_k; }
    else                { X = dtn; W = Wv; bias = bv; Y = g_v; }
    X += (size_t)b * C_ * N_;
    Y += (size_t)b * C_ * N_;

    const int m0 = blockIdx.y * 128;
    const int n0 = blockIdx.x * 128;

    __shared__ float As[8][128];
    __shared__ float Bs[8][128];

    const int tid = threadIdx.x;
    const int tx = tid & 15, ty = tid >> 4;

    // A load: W[m0+am][k0+ak .. +3] (float4), transposed store As[kk][m]
    const int am = tid >> 1;
    const int ak = (tid & 1) * 4;
    // B load: X[k0+bk][n0+bn .. +3] (float4), coalesced
    const int bkr = tid >> 5;
    const int bn  = (tid & 31) * 4;

    float acc[8][8] = {};

    for (int k0 = 0; k0 < C_; k0 += 8) {
        float4 av = *(const float4*)&W[(size_t)(m0 + am) * C_ + k0 + ak];
        float4 bv4 = *(const float4*)&X[(size_t)(k0 + bkr) * N_ + n0 + bn];
        __syncthreads();
        As[ak + 0][am] = av.x; As[ak + 1][am] = av.y;
        As[ak + 2][am] = av.z; As[ak + 3][am] = av.w;
        *(float4*)&Bs[bkr][bn] = bv4;
        __syncthreads();
#pragma unroll
        for (int kk = 0; kk < 8; kk++) {
            float ra[8], rb[8];
#pragma unroll
            for (int u = 0; u < 8; u++) ra[u] = As[kk][ty * 8 + u];
#pragma unroll
            for (int u = 0; u < 8; u++) rb[u] = Bs[kk][tx * 8 + u];
#pragma unroll
            for (int i = 0; i < 8; i++)
#pragma unroll
                for (int j = 0; j < 8; j++)
                    acc[i][j] += ra[i] * rb[j];
        }
    }

#pragma unroll
    for (int i = 0; i < 8; i++) {
        int m = m0 + ty * 8 + i;
        float bb = bias[m];
        float* yrow = &Y[(size_t)m * N_ + n0 + tx * 8];
        float4 v0 = make_float4(acc[i][0] + bb, acc[i][1] + bb,
                                acc[i][2] + bb, acc[i][3] + bb);
        float4 v1 = make_float4(acc[i][4] + bb, acc[i][5] + bb,
                                acc[i][6] + bb, acc[i][7] + bb);
        *(float4*)&yrow[0] = v0;
        *(float4*)&yrow[4] = v1;
    }
}

// ---------------------------------------------------------------------------
// Kernel 2: logits  L[i,j] = sum_d q[d,i]k[d,j] + sum_d p[d,i]q[d,j]
//   Fused as single GEMM: A = [Q;P] (128 x N), B = [K;Q] (128 x N), L = A^T B.
//   Both operands d-major (stride N), contiguous in i/j -> coalesced loads,
//   no transpose needed. grid = (8, 8, 64)
// ---------------------------------------------------------------------------
__global__ __launch_bounds__(256) void logits_kernel() {
    const int bh = blockIdx.z;
    const int h = bh & 7;
    const float* Qb = g_q + (size_t)bh * DH_ * N_;
    const float* Kb = g_k + (size_t)bh * DH_ * N_;
    const float* Pb = g_pos + (size_t)h * DH_ * N_;
    float* L = g_att + (size_t)bh * N_ * N_;

    const int i0 = blockIdx.y * 128;
    const int j0 = blockIdx.x * 128;

    __shared__ float As[8][128];
    __shared__ float Bs[8][128];

    const int tid = threadIdx.x;
    const int tx = tid & 15, ty = tid >> 4;
    const int lk = tid >> 5;         // 0..7  (row of k-tile)
    const int ln = (tid & 31) * 4;   // 0..124

    float acc[8][8] = {};

    for (int k0 = 0; k0 < 2 * DH_; k0 += 8) {
        int dd = k0 + lk;
        const float* arow = (dd < DH_) ? &Qb[(size_t)dd * N_ + i0]
                                       : &Pb[(size_t)(dd - DH_) * N_ + i0];
        const float* brow = (dd < DH_) ? &Kb[(size_t)dd * N_ + j0]
                                       : &Qb[(size_t)(dd - DH_) * N_ + j0];
        float4 av  = *(const float4*)&arow[ln];
        float4 bv4 = *(const float4*)&brow[ln];
        __syncthreads();
        *(float4*)&As[lk][ln] = av;
        *(float4*)&Bs[lk][ln] = bv4;
        __syncthreads();
#pragma unroll
        for (int kk = 0; kk < 8; kk++) {
            float ra[8], rb[8];
#pragma unroll
            for (int u = 0; u < 8; u++) ra[u] = As[kk][ty * 8 + u];
#pragma unroll
            for (int u = 0; u < 8; u++) rb[u] = Bs[kk][tx * 8 + u];
#pragma unroll
            for (int i = 0; i < 8; i++)
#pragma unroll
                for (int j = 0; j < 8; j++)
                    acc[i][j] += ra[i] * rb[j];
        }
    }

#pragma unroll
    for (int i = 0; i < 8; i++) {
        float* lrow = &L[(size_t)(i0 + ty * 8 + i) * N_ + j0 + tx * 8];
        *(float4*)&lrow[0] = make_float4(acc[i][0], acc[i][1], acc[i][2], acc[i][3]);
        *(float4*)&lrow[4] = make_float4(acc[i][4], acc[i][5], acc[i][6], acc[i][7]);
    }
}

// ---------------------------------------------------------------------------
// Kernel 3: row softmax on g_att (rows of 1024). One warp per row.
// ---------------------------------------------------------------------------
__global__ __launch_bounds__(256) void softmax_kernel() {
    const int warp = (blockIdx.x * blockDim.x + threadIdx.x) >> 5;
    const int lane = threadIdx.x & 31;
    if (warp >= B_ * HEADS_ * N_) return;
    float* row = g_att + (size_t)warp * N_;

    float v[32];
    float mx = -1e30f;
#pragma unroll
    for (int t = 0; t < 32; t++) {
        v[t] = row[lane + t * 32];
        mx = fmaxf(mx, v[t]);
    }
#pragma unroll
    for (int o = 16; o; o >>= 1) mx = fmaxf(mx, __shfl_xor_sync(0xffffffffu, mx, o));
    float s = 0.f;
#pragma unroll
    for (int t = 0; t < 32; t++) {
        v[t] = __expf(v[t] - mx);
        s += v[t];
    }
#pragma unroll
    for (int o = 16; o; o >>= 1) s += __shfl_xor_sync(0xffffffffu, s, o);
    float inv = 1.f / s;
#pragma unroll
    for (int t = 0; t < 32; t++) row[lane + t * 32] = v[t] * inv;
}

// ---------------------------------------------------------------------------
// Kernel 4: O[d,i] = sum_j V[d,j] * A[i,j]   (per bh)
//   SGEMM form: M=i (128 tile), K=j (tile 8), Nn=d (64).
//   A-operand = att[i][j] (row-major, transpose-store), B-operand = V[d][j]
//   (transpose-store). Output written directly into d_out ([B][C][N]).
//   grid = (8, 1, 64). 256 threads, microtile 8(i) x 4(d).
// ---------------------------------------------------------------------------
__global__ __launch_bounds__(256) void out_kernel(float* __restrict__ out) {
    const int bh = blockIdx.z;
    const float* Vb = g_v + (size_t)bh * DH_ * N_;
    const float* A = g_att + (size_t)bh * N_ * N_;
    float* O = out + (size_t)bh * DH_ * N_;   // c = h*64+d  ->  bh*64 + d

    const int i0 = blockIdx.x * 128;

    __shared__ float As[8][128];      // [jj][i]
    __shared__ float Bs[8][68];       // [jj][d]  (padded)

    const int tid = threadIdx.x;
    const int tx = tid & 15, ty = tid >> 4;   // tx -> d (4 each), ty -> i (8 each)

    const int ai = tid >> 1;            // 0..127  (i row)
    const int aj = (tid & 1) * 4;       // 0 or 4
    const int vd = tid >> 1;            // 0..127 but only <64 used
    const int vj = (tid & 1) * 4;

    float acc[8][4] = {};

    for (int k0 = 0; k0 < N_; k0 += 8) {
        float4 av = *(const float4*)&A[(size_t)(i0 + ai) * N_ + k0 + aj];
        float4 vv = make_float4(0.f, 0.f, 0.f, 0.f);
        if (vd < DH_)
            vv = *(const float4*)&Vb[(size_t)vd * N_ + k0 + vj];
        __syncthreads();
        As[aj + 0][ai] = av.x; As[aj + 1][ai] = av.y;
        As[aj + 2][ai] = av.z; As[aj + 3][ai] = av.w;
        if (vd < DH_) {
            Bs[vj + 0][vd] = vv.x; Bs[vj + 1][vd] = vv.y;
            Bs[vj + 2][vd] = vv.z; Bs[vj + 3][vd] = vv.w;
        }
        __syncthreads();
#pragma unroll
        for (int kk = 0; kk < 8; kk++) {
            float ra[8], rb[4];
#pragma unroll
            for (int u = 0; u < 8; u++) ra[u] = As[kk][ty * 8 + u];
#pragma unroll
            for (int u = 0; u < 4; u++) rb[u] = Bs[kk][tx * 4 + u];
#pragma unroll
            for (int i = 0; i < 8; i++)
#pragma unroll
                for (int j = 0; j < 4; j++)
                    acc[i][j] += ra[i] * rb[j];
        }
    }

    // O[d][i]: for each of this thread's 4 d-rows, 8 consecutive i... note
    // acc is [i-frag][d-frag]; write scalar (i contiguous per d row would
    // need acc transposed). Write per (d,i) pair: i = i0+ty*8+ii contiguous
    // along ii for fixed d -> gather into float4s per d row.
#pragma unroll
    for (int j = 0; j < 4; j++) {
        int d = tx * 4 + j;
        float* orow = &O[(size_t)d * N_ + i0 + ty * 8];
        float4 v0 = make_float4(acc[0][j], acc[1][j], acc[2][j], acc[3][j]);
        float4 v1 = make_float4(acc[4][j], acc[5][j], acc[6][j], acc[7][j]);
        *(float4*)&orow[0] = v0;
        *(float4*)&orow[4] = v1;
    }
}

// ---------------------------------------------------------------------------
// Launch
// ---------------------------------------------------------------------------
extern "C" void kernel_launch(void* const* d_in, const int* in_sizes, int n_in,
                              void* d_out, int out_size) {
    const float* x     = (const float*)d_in[0];
    const float* dtn   = (const float*)d_in[1];
    const float* Wq    = (const float*)d_in[2];
    const float* bq    = (const float*)d_in[3];
    const float* Wk    = (const float*)d_in[4];
    const float* bk    = (const float*)d_in[5];
    const float* Wv    = (const float*)d_in[6];
    const float* bv    = (const float*)d_in[7];
    const float* rel_h = (const float*)d_in[8];
    const float* rel_w = (const float*)d_in[9];
    float* out = (float*)d_out;

    // pos precompute: HEADS*DH*N = 524288 elems
    pos_kernel<<<(HEADS_ * DH_ * N_ + 255) / 256, 256>>>(rel_h, rel_w);

    // projections: grid (N/128, C/128, 3*B)
    proj_kernel<<<dim3(N_ / 128, C_ / 128, 3 * B_), 256>>>(
        x, dtn, Wq, bq, Wk, bk, Wv, bv);

    // logits: grid (N/128, N/128, B*HEADS)
    logits_kernel<<<dim3(N_ / 128, N_ / 128, B_ * HEADS_), 256>>>();

    // softmax: 65536 rows, 8 warps per 256-thread block
    softmax_kernel<<<(B_ * HEADS_ * N_) / 8, 256>>>();

    // output: grid (N/128, 1, B*HEADS)
    out_kernel<<<dim3(N_ / 128, 1, B_ * HEADS_), 256>>>(out);
}

// round 2
// speedup vs baseline: 1.0014x; 1.0014x over previous
#include <cuda_runtime.h>
#include <cuda_bf16.h>
#include <cstdint>

// Problem constants
#define B_    8
#define C_    512
#define N_    1024     // W*H = 32*32
#define HEADS_ 8
#define DH_   64
#define WSP_  32       // spatial W
#define HSP_  32       // spatial H

// ---------------------------------------------------------------------------
// Scratch (static device globals — no allocation in kernel_launch)
// ---------------------------------------------------------------------------
__device__ float g_q[B_ * C_ * N_];            // [b][h*64+d][n]  (16.8 MB)
__device__ float g_k[B_ * C_ * N_];
__device__ float g_v[B_ * C_ * N_];
__device__ float g_pos[HEADS_ * DH_ * N_];     // [h][d][n]       (2 MB)
__device__ float g_att[(size_t)B_ * HEADS_ * N_ * N_];  // [bh][i][j] (256 MB)

// ---------------------------------------------------------------------------
// Kernel 0: pos[h][d][n] = rel_h[h][d][hh] + rel_w[h][d][ww],  n = ww*32 + hh
// ---------------------------------------------------------------------------
__global__ void pos_kernel(const float* __restrict__ rel_h,
                           const float* __restrict__ rel_w) {
    int idx = blockIdx.x * blockDim.x + threadIdx.x;
    if (idx >= HEADS_ * DH_ * N_) return;
    int n = idx & (N_ - 1);
    int d = (idx >> 10) & (DH_ - 1);
    int h = idx >> 16;
    int ww = n >> 5;     // n = ww*HSP_ + hh
    int hh = n & 31;
    // rel_h: (1, HEADS, DH, 1, HSP_)  -> [h][d][hh]
    // rel_w: (1, HEADS, DH, WSP_, 1)  -> [h][d][ww]
    g_pos[idx] = rel_h[(h * DH_ + d) * HSP_ + hh] +
                 rel_w[(h * DH_ + d) * WSP_ + ww];
}

// ---------------------------------------------------------------------------
// Kernel 1: projections  Y_b = W @ X_b + bias   (per batch, per proj)
//   X: [B][C][N] row-major (N contiguous), W: [C][C] row-major, Y same as X.
//   128x128 tile, K-step 8, 256 threads, 8x8 microtile.
//   grid = (N/128=8, C/128=4, 3*B=24)
// ---------------------------------------------------------------------------
__global__ __launch_bounds__(256) void proj_kernel(
    const float* __restrict__ x, const float* __restrict__ dtn,
    const float* __restrict__ Wq, const float* __restrict__ bq,
    const float* __restrict__ Wk, const float* __restrict__ bk,
    const float* __restrict__ Wv, const float* __restrict__ bv) {
    int z = blockIdx.z;
    int proj = z >> 3, b = z & 7;
    const float* X; const float* W; const float* bias; float* Y;
    if (proj == 0)      { X = x;   W = Wq; bias = bq; Y = g_q; }
    else if (proj == 1) { X = dtn; W = Wk; bias = bk; Y = g_k; }
    else                { X = dtn; W = Wv; bias = bv; Y = g_v; }
    X += (size_t)b * C_ * N_;
    Y += (size_t)b * C_ * N_;

    const int m0 = blockIdx.y * 128;
    const int n0 = blockIdx.x * 128;

    __shared__ float As[8][128];
    __shared__ float Bs[8][128];

    const int tid = threadIdx.x;
    const int tx = tid & 15, ty = tid >> 4;

    // A load: W[m0+am][k0+ak .. +3] (float4), transposed store As[kk][m]
    const int am = tid >> 1;
    const int ak = (tid & 1) * 4;
    // B load: X[k0+bk][n0+bn .. +3] (float4), coalesced
    const int bkr = tid >> 5;
    const int bn  = (tid & 31) * 4;

    float acc[8][8] = {};

    for (int k0 = 0; k0 < C_; k0 += 8) {
        float4 av = *(const float4*)&W[(size_t)(m0 + am) * C_ + k0 + ak];
        float4 bv4 = *(const float4*)&X[(size_t)(k0 + bkr) * N_ + n0 + bn];
        __syncthreads();
        As[ak + 0][am] = av.x; As[ak + 1][am] = av.y;
        As[ak + 2][am] = av.z; As[ak + 3][am] = av.w;
        *(float4*)&Bs[bkr][bn] = bv4;
        __syncthreads();
#pragma unroll
        for (int kk = 0; kk < 8; kk++) {
            float ra[8], rb[8];
#pragma unroll
            for (int u = 0; u < 8; u++) ra[u] = As[kk][ty * 8 + u];
#pragma unroll
            for (int u = 0; u < 8; u++) rb[u] = Bs[kk][tx * 8 + u];
#pragma unroll
            for (int i = 0; i < 8; i++)
#pragma unroll
                for (int j = 0; j < 8; j++)
                    acc[i][j] += ra[i] * rb[j];
        }
    }

#pragma unroll
    for (int i = 0; i < 8; i++) {
        int m = m0 + ty * 8 + i;
        float bb = bias[m];
        float* yrow = &Y[(size_t)m * N_ + n0 + tx * 8];
        float4 v0 = make_float4(acc[i][0] + bb, acc[i][1] + bb,
                                acc[i][2] + bb, acc[i][3] + bb);
        float4 v1 = make_float4(acc[i][4] + bb, acc[i][5] + bb,
                                acc[i][6] + bb, acc[i][7] + bb);
        *(float4*)&yrow[0] = v0;
        *(float4*)&yrow[4] = v1;
    }
}

// ---------------------------------------------------------------------------
// Kernel 2: logits  L[i,j] = sum_d q[d,i]k[d,j] + sum_d p[d,i]q[d,j]
//   Fused as single GEMM: A = [Q;P] (128 x N), B = [K;Q] (128 x N), L = A^T B.
//   Both operands d-major (stride N), contiguous in i/j -> coalesced loads,
//   no transpose needed. grid = (8, 8, 64)
// ---------------------------------------------------------------------------
__global__ __launch_bounds__(256) void logits_kernel() {
    const int bh = blockIdx.z;
    const int h = bh & 7;
    const float* Qb = g_q + (size_t)bh * DH_ * N_;
    const float* Kb = g_k + (size_t)bh * DH_ * N_;
    const float* Pb = g_pos + (size_t)h * DH_ * N_;
    float* L = g_att + (size_t)bh * N_ * N_;

    const int i0 = blockIdx.y * 128;
    const int j0 = blockIdx.x * 128;

    __shared__ float As[8][128];
    __shared__ float Bs[8][128];

    const int tid = threadIdx.x;
    const int tx = tid & 15, ty = tid >> 4;
    const int lk = tid >> 5;         // 0..7  (row of k-tile)
    const int ln = (tid & 31) * 4;   // 0..124

    float acc[8][8] = {};

    for (int k0 = 0; k0 < 2 * DH_; k0 += 8) {
        int dd = k0 + lk;
        const float* arow = (dd < DH_) ? &Qb[(size_t)dd * N_ + i0]
                                       : &Pb[(size_t)(dd - DH_) * N_ + i0];
        const float* brow = (dd < DH_) ? &Kb[(size_t)dd * N_ + j0]
                                       : &Qb[(size_t)(dd - DH_) * N_ + j0];
        float4 av  = *(const float4*)&arow[ln];
        float4 bv4 = *(const float4*)&brow[ln];
        __syncthreads();
        *(float4*)&As[lk][ln] = av;
        *(float4*)&Bs[lk][ln] = bv4;
        __syncthreads();
#pragma unroll
        for (int kk = 0; kk < 8; kk++) {
            float ra[8], rb[8];
#pragma unroll
            for (int u = 0; u < 8; u++) ra[u] = As[kk][ty * 8 + u];
#pragma unroll
            for (int u = 0; u < 8; u++) rb[u] = Bs[kk][tx * 8 + u];
#pragma unroll
            for (int i = 0; i < 8; i++)
#pragma unroll
                for (int j = 0; j < 8; j++)
                    acc[i][j] += ra[i] * rb[j];
        }
    }

#pragma unroll
    for (int i = 0; i < 8; i++) {
        float* lrow = &L[(size_t)(i0 + ty * 8 + i) * N_ + j0 + tx * 8];
        *(float4*)&lrow[0] = make_float4(acc[i][0], acc[i][1], acc[i][2], acc[i][3]);
        *(float4*)&lrow[4] = make_float4(acc[i][4], acc[i][5], acc[i][6], acc[i][7]);
    }
}

// ---------------------------------------------------------------------------
// Kernel 3: row softmax on g_att (rows of 1024). One warp per row.
// ---------------------------------------------------------------------------
__global__ __launch_bounds__(256) void softmax_kernel() {
    const int warp = (blockIdx.x * blockDim.x + threadIdx.x) >> 5;
    const int lane = threadIdx.x & 31;
    if (warp >= B_ * HEADS_ * N_) return;
    float* row = g_att + (size_t)warp * N_;

    float v[32];
    float mx = -1e30f;
#pragma unroll
    for (int t = 0; t < 32; t++) {
        v[t] = row[lane + t * 32];
        mx = fmaxf(mx, v[t]);
    }
#pragma unroll
    for (int o = 16; o; o >>= 1) mx = fmaxf(mx, __shfl_xor_sync(0xffffffffu, mx, o));
    float s = 0.f;
#pragma unroll
    for (int t = 0; t < 32; t++) {
        v[t] = __expf(v[t] - mx);
        s += v[t];
    }
#pragma unroll
    for (int o = 16; o; o >>= 1) s += __shfl_xor_sync(0xffffffffu, s, o);
    float inv = 1.f / s;
#pragma unroll
    for (int t = 0; t < 32; t++) row[lane + t * 32] = v[t] * inv;
}

// ---------------------------------------------------------------------------
// Kernel 4: O[d,i] = sum_j V[d,j] * A[i,j]   (per bh)
//   SGEMM form: M=i (128 tile), K=j (tile 8), Nn=d (64).
//   A-operand = att[i][j] (row-major, transpose-store), B-operand = V[d][j]
//   (transpose-store). Output written directly into d_out ([B][C][N]).
//   grid = (8, 1, 64). 256 threads, microtile 8(i) x 4(d).
// ---------------------------------------------------------------------------
__global__ __launch_bounds__(256) void out_kernel(float* __restrict__ out) {
    const int bh = blockIdx.z;
    const float* Vb = g_v + (size_t)bh * DH_ * N_;
    const float* A = g_att + (size_t)bh * N_ * N_;
    float* O = out + (size_t)bh * DH_ * N_;   // c = h*64+d  ->  bh*64 + d

    const int i0 = blockIdx.x * 128;

    __shared__ float As[8][128];      // [jj][i]
    __shared__ float Bs[8][68];       // [jj][d]  (padded)

    const int tid = threadIdx.x;
    const int tx = tid & 15, ty = tid >> 4;   // tx -> d (4 each), ty -> i (8 each)

    const int ai = tid >> 1;            // 0..127  (i row)
    const int aj = (tid & 1) * 4;       // 0 or 4
    const int vd = tid >> 1;            // 0..127 but only <64 used
    const int vj = (tid & 1) * 4;

    float acc[8][4] = {};

    for (int k0 = 0; k0 < N_; k0 += 8) {
        float4 av = *(const float4*)&A[(size_t)(i0 + ai) * N_ + k0 + aj];
        float4 vv = make_float4(0.f, 0.f, 0.f, 0.f);
        if (vd < DH_)
            vv = *(const float4*)&Vb[(size_t)vd * N_ + k0 + vj];
        __syncthreads();
        As[aj + 0][ai] = av.x; As[aj + 1][ai] = av.y;
        As[aj + 2][ai] = av.z; As[aj + 3][ai] = av.w;
        if (vd < DH_) {
            Bs[vj + 0][vd] = vv.x; Bs[vj + 1][vd] = vv.y;
            Bs[vj + 2][vd] = vv.z; Bs[vj + 3][vd] = vv.w;
        }
        __syncthreads();
#pragma unroll
        for (int kk = 0; kk < 8; kk++) {
            float ra[8], rb[4];
#pragma unroll
            for (int u = 0; u < 8; u++) ra[u] = As[kk][ty * 8 + u];
#pragma unroll
            for (int u = 0; u < 4; u++) rb[u] = Bs[kk][tx * 4 + u];
#pragma unroll
            for (int i = 0; i < 8; i++)
#pragma unroll
                for (int j = 0; j < 4; j++)
                    acc[i][j] += ra[i] * rb[j];
        }
    }

    // O[d][i]: for each of this thread's 4 d-rows, 8 consecutive i... note
    // acc is [i-frag][d-frag]; write scalar (i contiguous per d row would
    // need acc transposed). Write per (d,i) pair: i = i0+ty*8+ii contiguous
    // along ii for fixed d -> gather into float4s per d row.
#pragma unroll
    for (int j = 0; j < 4; j++) {
        int d = tx * 4 + j;
        float* orow = &O[(size_t)d * N_ + i0 + ty * 8];
        float4 v0 = make_float4(acc[0][j], acc[1][j], acc[2][j], acc[3][j]);
        float4 v1 = make_float4(acc[4][j], acc[5][j], acc[6][j], acc[7][j]);
        *(float4*)&orow[0] = v0;
        *(float4*)&orow[4] = v1;
    }
}

// ---------------------------------------------------------------------------
// Launch
// ---------------------------------------------------------------------------
extern "C" void kernel_launch(void* const* d_in, const int* in_sizes, int n_in,
                              void* d_out, int out_size) {
    const float* x     = (const float*)d_in[0];
    const float* dtn   = (const float*)d_in[1];
    const float* Wq    = (const float*)d_in[2];
    const float* bq    = (const float*)d_in[3];
    const float* Wk    = (const float*)d_in[4];
    const float* bk    = (const float*)d_in[5];
    const float* Wv    = (const float*)d_in[6];
    const float* bv    = (const float*)d_in[7];
    const float* rel_h = (const float*)d_in[8];
    const float* rel_w = (const float*)d_in[9];
    float* out = (float*)d_out;

    // pos precompute: HEADS*DH*N = 524288 elems
    pos_kernel<<<(HEADS_ * DH_ * N_ + 255) / 256, 256>>>(rel_h, rel_w);

    // projections: grid (N/128, C/128, 3*B)
    proj_kernel<<<dim3(N_ / 128, C_ / 128, 3 * B_), 256>>>(
        x, dtn, Wq, bq, Wk, bk, Wv, bv);

    // logits: grid (N/128, N/128, B*HEADS)
    logits_kernel<<<dim3(N_ / 128, N_ / 128, B_ * HEADS_), 256>>>();

    // softmax: 65536 rows, 8 warps per 256-thread block
    softmax_kernel<<<(B_ * HEADS_ * N_) / 8, 256>>>();

    // output: grid (N/128, 1, B*HEADS)
    out_kernel<<<dim3(N_ / 128, 1, B_ * HEADS_), 256>>>(out);
}

// round 4
// speedup vs baseline: 1.8102x; 1.8077x over previous
#include <cuda_runtime.h>
#include <cuda_bf16.h>
#include <cstdint>

#define B_ 8
#define C_ 512
#define N_ 1024
#define HEADS_ 8
#define DH_ 64
using bf16 = __nv_bfloat16;

// ------------------------------ helpers ------------------------------------
__device__ __forceinline__ uint32_t smem_u32(const void* p) {
    uint32_t a;
    asm("{ .reg .u64 t; cvta.to.shared.u64 t, %1; cvt.u32.u64 %0, t; }" : "=r"(a) : "l"(p));
    return a;
}
#define CP16(dst, src) asm volatile("cp.async.cg.shared.global [%0], [%1], 16;" :: "r"(dst), "l"(src) : "memory")
#define CP_COMMIT() asm volatile("cp.async.commit_group;" ::: "memory")
#define CP_WAIT(n) asm volatile("cp.async.wait_group %0;" :: "n"(n) : "memory")

__device__ __forceinline__ void ldm4(uint32_t (&r)[4], uint32_t addr) {
    asm volatile("ldmatrix.sync.aligned.m8n8.x4.shared.b16 {%0,%1,%2,%3}, [%4];"
                 : "=r"(r[0]), "=r"(r[1]), "=r"(r[2]), "=r"(r[3]) : "r"(addr));
}
__device__ __forceinline__ void mma16816(float (&d)[4], const uint32_t (&a)[4],
                                         const uint32_t (&b)[2]) {
    asm volatile("mma.sync.aligned.m16n8k16.row.col.f32.bf16.bf16.f32 "
                 "{%0,%1,%2,%3},{%4,%5,%6,%7},{%8,%9},{%0,%1,%2,%3};"
                 : "+f"(d[0]), "+f"(d[1]), "+f"(d[2]), "+f"(d[3])
                 : "r"(a[0]), "r"(a[1]), "r"(a[2]), "r"(a[3]), "r"(b[0]), "r"(b[1]));
}
__device__ __forceinline__ uint32_t pack2(float a, float b) {
    __nv_bfloat162 t = __floats2bfloat162_rn(a, b);
    return *(uint32_t*)&t;
}
__device__ __forceinline__ void split2(float v, float& hi, float& lo) {
    hi = __bfloat162float(__float2bfloat16(v));
    lo = v - hi;
}

// ------------------------------ scratch ------------------------------------
__device__ __align__(16) bf16 g_xt_hi[2 * B_ * N_ * C_];   // [src*8+b][n][c]
__device__ __align__(16) bf16 g_xt_lo[2 * B_ * N_ * C_];
__device__ __align__(16) bf16 g_w_hi[3 * C_ * C_];         // [proj][m][k]
__device__ __align__(16) bf16 g_w_lo[3 * C_ * C_];
__device__ __align__(16) bf16 g_qt_hi[B_ * HEADS_ * N_ * DH_];  // [bh][n][d]
__device__ __align__(16) bf16 g_qt_lo[B_ * HEADS_ * N_ * DH_];
__device__ __align__(16) bf16 g_kt_hi[B_ * HEADS_ * N_ * DH_];
__device__ __align__(16) bf16 g_kt_lo[B_ * HEADS_ * N_ * DH_];
__device__ __align__(16) bf16 g_v_hi[B_ * HEADS_ * DH_ * N_];   // [bh][d][n]
__device__ __align__(16) bf16 g_v_lo[B_ * HEADS_ * DH_ * N_];
__device__ __align__(16) bf16 g_p_hi[HEADS_ * N_ * DH_];        // [h][n][d]
__device__ __align__(16) bf16 g_p_lo[HEADS_ * N_ * DH_];
__device__ __align__(16) float g_att[(size_t)B_ * HEADS_ * N_ * N_];

// ------------------------------ prep ---------------------------------------
__global__ __launch_bounds__(256) void tsplit_kernel(const float* __restrict__ x,
                                                     const float* __restrict__ dt) {
    int z = blockIdx.z, b = z & 7, src = z >> 3;
    const float* X = (src ? dt : x) + (size_t)b * C_ * N_;
    __shared__ float t[32][33];
    int c0 = blockIdx.x * 32, n0 = blockIdx.y * 32;
    int tx = threadIdx.x & 31, ty = threadIdx.x >> 5;
#pragma unroll
    for (int i = 0; i < 4; i++) t[ty + i * 8][tx] = X[(size_t)(c0 + ty + i * 8) * N_ + n0 + tx];
    __syncthreads();
    bf16* dh = g_xt_hi + ((size_t)z * N_ + n0) * C_ + c0;
    bf16* dl = g_xt_lo + ((size_t)z * N_ + n0) * C_ + c0;
#pragma unroll
    for (int i = 0; i < 4; i++) {
        int n = ty + i * 8;
        float hi, lo;
        split2(t[tx][n], hi, lo);
        dh[(size_t)n * C_ + tx] = __float2bfloat16(hi);
        dl[(size_t)n * C_ + tx] = __float2bfloat16(lo);
    }
}
__global__ __launch_bounds__(256) void wsplit_kernel(const float* __restrict__ Wq,
                                                     const float* __restrict__ Wk,
                                                     const float* __restrict__ Wv) {
    int idx = blockIdx.x * 256 + threadIdx.x;
    if (idx >= 3 * C_ * C_) return;
    int p = idx / (C_ * C_);
    float v = (p == 0 ? Wq : p == 1 ? Wk : Wv)[idx - p * C_ * C_];
    float hi, lo;
    split2(v, hi, lo);
    g_w_hi[idx] = __float2bfloat16(hi);
    g_w_lo[idx] = __float2bfloat16(lo);
}
__global__ __launch_bounds__(256) void psplit_kernel(const float* __restrict__ rel_h,
                                                     const float* __restrict__ rel_w) {
    int idx = blockIdx.x * 256 + threadIdx.x;  // [h][n][d]
    if (idx >= HEADS_ * N_ * DH_) return;
    int d = idx & 63, n = (idx >> 6) & 1023, h = idx >> 16;
    float v = rel_h[(h * DH_ + d) * 32 + (n & 31)] + rel_w[(h * DH_ + d) * 32 + (n >> 5)];
    float hi, lo;
    split2(v, hi, lo);
    g_p_hi[idx] = __float2bfloat16(hi);
    g_p_lo[idx] = __float2bfloat16(lo);
}

// ---------------- generic mma.sync GEMM core (128x128, K-chunks of 64) -----
// smem buffers: buf{0,1}: A @ buf*36864 (128 rows x 144B), B @ +18432.
template <int NCH, typename F>
__device__ __forceinline__ void gemm_mma(char* smem, int tid, float acc[2][8][4], F fetch) {
    const int lane = tid & 31, wid = tid >> 5;
    const int wm0 = (wid & 3) * 32, wn0 = (wid >> 2) * 64;
    const uint32_t sb = smem_u32(smem);
    auto issue = [&](int buf, const bf16* pa, int sa, const bf16* pb, int sbs) {
        uint32_t da = sb + buf * 36864, db = da + 18432;
#pragma unroll
        for (int i = 0; i < 4; i++) {
            int s = tid + i * 256, r = s >> 3, seg = s & 7;
            CP16(da + r * 144 + seg * 16, pa + (size_t)r * sa + seg * 8);
            CP16(db + r * 144 + seg * 16, pb + (size_t)r * sbs + seg * 8);
        }
        CP_COMMIT();
    };
    {
        const bf16 *pa, *pb;
        int sa, sbs;
        fetch(0, pa, sa, pb, sbs);
        issue(0, pa, sa, pb, sbs);
    }
    for (int c = 0; c < NCH; c++) {
        if (c + 1 < NCH) {
            const bf16 *pa, *pb;
            int sa, sbs;
            fetch(c + 1, pa, sa, pb, sbs);
            issue((c + 1) & 1, pa, sa, pb, sbs);
            CP_WAIT(1);
        } else {
            CP_WAIT(0);
        }
        __syncthreads();
        uint32_t da = sb + (c & 1) * 36864, db = da + 18432;
#pragma unroll
        for (int ks = 0; ks < 4; ks++) {
            uint32_t a[2][4], b[8][2];
#pragma unroll
            for (int mt = 0; mt < 2; mt++)
                ldm4(a[mt], da + (wm0 + mt * 16 + (lane & 15)) * 144 + ks * 32 + ((lane >> 4) << 4));
#pragma unroll
            for (int np = 0; np < 4; np++) {
                uint32_t r4[4];
                ldm4(r4, db + (wn0 + np * 16 + (lane & 7) + ((lane >> 4) << 3)) * 144 +
                             ks * 32 + (((lane >> 3) & 1) << 4));
                b[2 * np][0] = r4[0]; b[2 * np][1] = r4[1];
                b[2 * np + 1][0] = r4[2]; b[2 * np + 1][1] = r4[3];
            }
#pragma unroll
            for (int mt = 0; mt < 2; mt++)
#pragma unroll
                for (int nt = 0; nt < 8; nt++) mma16816(acc[mt][nt], a[mt], b[nt]);
        }
        __syncthreads();
    }
}

// ---------------- proj q/k: D[n][c] -> qt/kt[bh][n][d] hi/lo ---------------
__global__ __launch_bounds__(256, 1) void proj_qk_kernel(const float* __restrict__ bq,
                                                         const float* __restrict__ bk) {
    extern __shared__ char smem[];
    const int tid = threadIdx.x, z = blockIdx.z, proj = z >> 3, b = z & 7;
    const int m0 = blockIdx.x * 128, n0 = blockIdx.y * 128;
    float acc[2][8][4] = {};
    gemm_mma<24>(smem, tid, acc, [&](int c, const bf16*& pa, int& sa, const bf16*& pb, int& sbs) {
        int kb = c & 7, p = c >> 3;
        pa = (p == 2 ? g_xt_lo : g_xt_hi) + ((size_t)z * N_ + n0) * C_ + kb * 64;
        pb = (p == 1 ? g_w_lo : g_w_hi) + ((size_t)proj * C_ + m0) * C_ + kb * 64;
        sa = C_; sbs = C_;
    });
    const int lane = tid & 31, wid = tid >> 5;
    const int wm0 = (wid & 3) * 32, wn0 = (wid >> 2) * 64;
    const float* bias = proj ? bk : bq;
    bf16* dsth = proj ? g_kt_hi : g_qt_hi;
    bf16* dstl = proj ? g_kt_lo : g_qt_lo;
#pragma unroll
    for (int mt = 0; mt < 2; mt++)
#pragma unroll
        for (int rp = 0; rp < 2; rp++) {
            int n = n0 + wm0 + mt * 16 + (lane >> 2) + rp * 8;
#pragma unroll
            for (int nt = 0; nt < 8; nt++) {
                int cc = m0 + wn0 + nt * 8 + (lane & 3) * 2;
                float v0 = acc[mt][nt][2 * rp] + bias[cc];
                float v1 = acc[mt][nt][2 * rp + 1] + bias[cc + 1];
                float h0, l0, h1, l1;
                split2(v0, h0, l0);
                split2(v1, h1, l1);
                size_t base = (((size_t)(b * 8 + (cc >> 6))) * N_ + n) * DH_ + (cc & 63);
                *(uint32_t*)(dsth + base) = pack2(h0, h1);
                *(uint32_t*)(dstl + base) = pack2(l0, l1);
            }
        }
}

// ---------------- proj v: D[c][n] -> v[bh][d][n] hi/lo ---------------------
__global__ __launch_bounds__(256, 1) void proj_v_kernel(const float* __restrict__ bv) {
    extern __shared__ char smem[];
    const int tid = threadIdx.x, b = blockIdx.z;
    const int m0 = blockIdx.y * 128, n0 = blockIdx.x * 128;
    float acc[2][8][4] = {};
    gemm_mma<24>(smem, tid, acc, [&](int c, const bf16*& pa, int& sa, const bf16*& pb, int& sbs) {
        int kb = c & 7, p = c >> 3;
        pa = (p == 2 ? g_w_lo : g_w_hi) + ((size_t)2 * C_ + m0) * C_ + kb * 64;
        pb = (p == 1 ? g_xt_lo : g_xt_hi) + ((size_t)(8 + b) * N_ + n0) * C_ + kb * 64;
        sa = C_; sbs = C_;
    });
    const int lane = tid & 31, wid = tid >> 5;
    const int wm0 = (wid & 3) * 32, wn0 = (wid >> 2) * 64;
#pragma unroll
    for (int mt = 0; mt < 2; mt++)
#pragma unroll
        for (int rp = 0; rp < 2; rp++) {
            int cc = m0 + wm0 + mt * 16 + (lane >> 2) + rp * 8;
            float bb = bv[cc];
            size_t rbase = ((size_t)b * 8 + (cc >> 6)) * DH_ * N_ + (size_t)(cc & 63) * N_;
#pragma unroll
            for (int nt = 0; nt < 8; nt++) {
                int n = n0 + wn0 + nt * 8 + (lane & 3) * 2;
                float h0, l0, h1, l1;
                split2(acc[mt][nt][2 * rp] + bb, h0, l0);
                split2(acc[mt][nt][2 * rp + 1] + bb, h1, l1);
                *(uint32_t*)(g_v_hi + rbase + n) = pack2(h0, h1);
                *(uint32_t*)(g_v_lo + rbase + n) = pack2(l0, l1);
            }
        }
}

// ---------------- logits: L[i][j] = q_i.k_j + p_i.q_j (fp32 out) -----------
__global__ __launch_bounds__(256, 1) void logits_kernel() {
    extern __shared__ char smem[];
    const int tid = threadIdx.x, bh = blockIdx.z, h = bh & 7;
    const int i0 = blockIdx.y * 128, j0 = blockIdx.x * 128;
    const bf16* qhi_i = g_qt_hi + ((size_t)bh * N_ + i0) * DH_;
    const bf16* qlo_i = g_qt_lo + ((size_t)bh * N_ + i0) * DH_;
    const bf16* phi_i = g_p_hi + ((size_t)h * N_ + i0) * DH_;
    const bf16* plo_i = g_p_lo + ((size_t)h * N_ + i0) * DH_;
    const bf16* khi_j = g_kt_hi + ((size_t)bh * N_ + j0) * DH_;
    const bf16* klo_j = g_kt_lo + ((size_t)bh * N_ + j0) * DH_;
    const bf16* qhi_j = g_qt_hi + ((size_t)bh * N_ + j0) * DH_;
    const bf16* qlo_j = g_qt_lo + ((size_t)bh * N_ + j0) * DH_;
    const bf16* Aarr[6] = {qhi_i, phi_i, qhi_i, qlo_i, phi_i, plo_i};
    const bf16* Barr[6] = {khi_j, qhi_j, klo_j, khi_j, qlo_j, qhi_j};
    float acc[2][8][4] = {};
    gemm_mma<6>(smem, tid, acc, [&](int c, const bf16*& pa, int& sa, const bf16*& pb, int& sbs) {
        pa = Aarr[c]; pb = Barr[c]; sa = DH_; sbs = DH_;
    });
    const int lane = tid & 31, wid = tid >> 5;
    const int wm0 = (wid & 3) * 32, wn0 = (wid >> 2) * 64;
    float* L = g_att + (size_t)bh * N_ * N_;
#pragma unroll
    for (int mt = 0; mt < 2; mt++)
#pragma unroll
        for (int rp = 0; rp < 2; rp++) {
            int i = i0 + wm0 + mt * 16 + (lane >> 2) + rp * 8;
#pragma unroll
            for (int nt = 0; nt < 8; nt++) {
                int j = j0 + wn0 + nt * 8 + (lane & 3) * 2;
                *(float2*)&L[(size_t)i * N_ + j] =
                    make_float2(acc[mt][nt][2 * rp], acc[mt][nt][2 * rp + 1]);
            }
        }
}

// ---------------- softmax --------------------------------------------------
__global__ __launch_bounds__(256) void softmax_kernel() {
    const int warp = (blockIdx.x * blockDim.x + threadIdx.x) >> 5;
    const int lane = threadIdx.x & 31;
    if (warp >= B_ * HEADS_ * N_) return;
    float* row = g_att + (size_t)warp * N_;
    float v[32], mx = -1e30f;
#pragma unroll
    for (int t = 0; t < 32; t++) { v[t] = row[lane + t * 32]; mx = fmaxf(mx, v[t]); }
#pragma unroll
    for (int o = 16; o; o >>= 1) mx = fmaxf(mx, __shfl_xor_sync(~0u, mx, o));
    float s = 0.f;
#pragma unroll
    for (int t = 0; t < 32; t++) { v[t] = __expf(v[t] - mx); s += v[t]; }
#pragma unroll
    for (int o = 16; o; o >>= 1) s += __shfl_xor_sync(~0u, s, o);
    float inv = 1.f / s;
#pragma unroll
    for (int t = 0; t < 32; t++) row[lane + t * 32] = v[t] * inv;
}

// ---------------- out: O[d][i] = sum_j att[i][j] v[d][j] -------------------
// smem: Ahi@0 Alo@18432 Vh@36864 Vl@46080 (55296 B); reused for transpose.
__global__ __launch_bounds__(256, 1) void out_kernel(float* __restrict__ out) {
    extern __shared__ char smem[];
    const int tid = threadIdx.x, bh = blockIdx.z;
    const int i0 = blockIdx.x * 128;
    const int lane = tid & 31, wid = tid >> 5;
    const int wm0 = (wid & 3) * 32, wn0 = (wid >> 2) * 32;
    const uint32_t sb = smem_u32(smem);
    const float* A = g_att + ((size_t)bh * N_ + i0) * N_;
    const bf16* Vh = g_v_hi + (size_t)bh * DH_ * N_;
    const bf16* Vl = g_v_lo + (size_t)bh * DH_ * N_;
    float acc[2][4][4] = {};
    for (int c = 0; c < 16; c++) {
        const int j0 = c * 64;
        float4 va[8], vh[2], vl[2];
#pragma unroll
        for (int i = 0; i < 8; i++) {
            int s = tid + i * 256;
            va[i] = *(const float4*)(A + (size_t)(s >> 4) * N_ + j0 + ((s & 15) << 2));
        }
#pragma unroll
        for (int i = 0; i < 2; i++) {
            int s = tid + i * 256;
            vh[i] = *(const float4*)(Vh + (size_t)(s >> 3) * N_ + j0 + ((s & 7) << 3));
            vl[i] = *(const float4*)(Vl + (size_t)(s >> 3) * N_ + j0 + ((s & 7) << 3));
        }
        __syncthreads();
#pragma unroll
        for (int i = 0; i < 8; i++) {
            int s = tid + i * 256;
            uint32_t off = (uint32_t)((s >> 4) * 144 + ((s & 15) << 3));
            float h0, l0, h1, l1, h2, l2, h3, l3;
            split2(va[i].x, h0, l0); split2(va[i].y, h1, l1);
            split2(va[i].z, h2, l2); split2(va[i].w, h3, l3);
            *(uint2*)(smem + off) = make_uint2(pack2(h0, h1), pack2(h2, h3));
            *(uint2*)(smem + 18432 + off) = make_uint2(pack2(l0, l1), pack2(l2, l3));
        }
#pragma unroll
        for (int i = 0; i < 2; i++) {
            int s = tid + i * 256;
            uint32_t off = (uint32_t)((s >> 3) * 144 + ((s & 7) << 4));
            *(float4*)(smem + 36864 + off) = vh[i];
            *(float4*)(smem + 46080 + off) = vl[i];
        }
        __syncthreads();
#pragma unroll
        for (int ks = 0; ks < 4; ks++) {
            uint32_t ah[2][4], al[2][4], bh2[4][2], bl2[4][2];
#pragma unroll
            for (int mt = 0; mt < 2; mt++) {
                uint32_t roff = (wm0 + mt * 16 + (lane & 15)) * 144 + ks * 32 + ((lane >> 4) << 4);
                ldm4(ah[mt], sb + roff);
                ldm4(al[mt], sb + 18432 + roff);
            }
#pragma unroll
            for (int np = 0; np < 2; np++) {
                uint32_t roff = (wn0 + np * 16 + (lane & 7) + ((lane >> 4) << 3)) * 144 +
                                ks * 32 + (((lane >> 3) & 1) << 4);
                uint32_t r4[4];
                ldm4(r4, sb + 36864 + roff);
                bh2[2 * np][0] = r4[0]; bh2[2 * np][1] = r4[1];
                bh2[2 * np + 1][0] = r4[2]; bh2[2 * np + 1][1] = r4[3];
                ldm4(r4, sb + 46080 + roff);
                bl2[2 * np][0] = r4[0]; bl2[2 * np][1] = r4[1];
                bl2[2 * np + 1][0] = r4[2]; bl2[2 * np + 1][1] = r4[3];
            }
#pragma unroll
            for (int mt = 0; mt < 2; mt++)
#pragma unroll
                for (int nt = 0; nt < 4; nt++) {
                    mma16816(acc[mt][nt], ah[mt], bh2[nt]);
                    mma16816(acc[mt][nt], ah[mt], bl2[nt]);
                    mma16816(acc[mt][nt], al[mt], bh2[nt]);
                }
        }
        __syncthreads();
    }
    // transpose via smem: tr[d][i] (pad 136)
    float* tr = (float*)smem;
#pragma unroll
    for (int mt = 0; mt < 2; mt++)
#pragma unroll
        for (int rp = 0; rp < 2; rp++) {
            int i = wm0 + mt * 16 + (lane >> 2) + rp * 8;
#pragma unroll
            for (int nt = 0; nt < 4; nt++) {
                int d = wn0 + nt * 8 + (lane & 3) * 2;
                tr[d * 136 + i] = acc[mt][nt][2 * rp];
                tr[(d + 1) * 136 + i] = acc[mt][nt][2 * rp + 1];
            }
        }
    __syncthreads();
#pragma unroll
    for (int i = 0; i < 8; i++) {
        int s = tid + i * 256, d = s >> 5, seg = s & 31;
        *(float4*)(out + ((size_t)bh * DH_ + d) * N_ + i0 + seg * 4) =
            *(float4*)(tr + d * 136 + seg * 4);
    }
}

// ------------------------------ launch -------------------------------------
extern "C" void kernel_launch(void* const* d_in, const int* in_sizes, int n_in,
                              void* d_out, int out_size) {
    const float* x = (const float*)d_in[0];
    const float* dtn = (const float*)d_in[1];
    const float* Wq = (const float*)d_in[2];
    const float* bq = (const float*)d_in[3];
    const float* Wk = (const float*)d_in[4];
    const float* bk = (const float*)d_in[5];
    const float* Wv = (const float*)d_in[6];
    const float* bv = (const float*)d_in[7];
    const float* rel_h = (const float*)d_in[8];
    const float* rel_w = (const float*)d_in[9];
    float* out = (float*)d_out;

    const int SM_GEMM = 73728, SM_OUT = 55296;
    static int once = 0;
    if (!once) {
        once = 1;
        cudaFuncSetAttribute(proj_qk_kernel, cudaFuncAttributeMaxDynamicSharedMemorySize, SM_GEMM);
        cudaFuncSetAttribute(proj_v_kernel, cudaFuncAttributeMaxDynamicSharedMemorySize, SM_GEMM);
        cudaFuncSetAttribute(logits_kernel, cudaFuncAttributeMaxDynamicSharedMemorySize, SM_GEMM);
        cudaFuncSetAttribute(out_kernel, cudaFuncAttributeMaxDynamicSharedMemorySize, SM_OUT);
    }

    tsplit_kernel<<<dim3(C_ / 32, N_ / 32, 16), 256>>>(x, dtn);
    wsplit_kernel<<<(3 * C_ * C_ + 255) / 256, 256>>>(Wq, Wk, Wv);
    psplit_kernel<<<(HEADS_ * N_ * DH_ + 255) / 256, 256>>>(rel_h, rel_w);
    proj_qk_kernel<<<dim3(C_ / 128, N_ / 128, 16), 256, SM_GEMM>>>(bq, bk);
    proj_v_kernel<<<dim3(N_ / 128, C_ / 128, B_), 256, SM_GEMM>>>(bv);
    logits_kernel<<<dim3(N_ / 128, N_ / 128, B_ * HEADS_), 256, SM_GEMM>>>();
    softmax_kernel<<<(B_ * HEADS_ * N_) / 8, 256>>>();
    out_kernel<<<dim3(N_ / 128, 1, B_ * HEADS_), 256, SM_OUT>>>(out);
}

// round 5
// speedup vs baseline: 2.6054x; 1.4393x over previous
#include <cuda_runtime.h>
#include <cuda_bf16.h>
#include <cstdint>

#define B_ 8
#define C_ 512
#define N_ 1024
#define HEADS_ 8
#define DH_ 64
using bf16 = __nv_bfloat16;

// ------------------------------ helpers ------------------------------------
__device__ __forceinline__ uint32_t smem_u32(const void* p) {
    uint32_t a;
    asm("{ .reg .u64 t; cvta.to.shared.u64 t, %1; cvt.u32.u64 %0, t; }" : "=r"(a) : "l"(p));
    return a;
}
#define CP16(dst, src) asm volatile("cp.async.cg.shared.global [%0], [%1], 16;" :: "r"(dst), "l"(src) : "memory")
#define CP_COMMIT() asm volatile("cp.async.commit_group;" ::: "memory")
#define CP_WAIT(n) asm volatile("cp.async.wait_group %0;" :: "n"(n) : "memory")

__device__ __forceinline__ void ldm4(uint32_t (&r)[4], uint32_t addr) {
    asm volatile("ldmatrix.sync.aligned.m8n8.x4.shared.b16 {%0,%1,%2,%3}, [%4];"
                 : "=r"(r[0]), "=r"(r[1]), "=r"(r[2]), "=r"(r[3]) : "r"(addr));
}
__device__ __forceinline__ void mma16816(float (&d)[4], const uint32_t (&a)[4],
                                         const uint32_t (&b)[2]) {
    asm volatile("mma.sync.aligned.m16n8k16.row.col.f32.bf16.bf16.f32 "
                 "{%0,%1,%2,%3},{%4,%5,%6,%7},{%8,%9},{%0,%1,%2,%3};"
                 : "+f"(d[0]), "+f"(d[1]), "+f"(d[2]), "+f"(d[3])
                 : "r"(a[0]), "r"(a[1]), "r"(a[2]), "r"(a[3]), "r"(b[0]), "r"(b[1]));
}
__device__ __forceinline__ uint32_t pack2(float a, float b) {
    __nv_bfloat162 t = __floats2bfloat162_rn(a, b);
    return *(uint32_t*)&t;
}
__device__ __forceinline__ void split2(float v, float& hi, float& lo) {
    hi = __bfloat162float(__float2bfloat16(v));
    lo = v - hi;
}

// ------------------------------ scratch ------------------------------------
__device__ __align__(16) bf16 g_xt_hi[2 * B_ * N_ * C_];   // [src*8+b][n][c]
__device__ __align__(16) bf16 g_xt_lo[2 * B_ * N_ * C_];
__device__ __align__(16) bf16 g_w_hi[3 * C_ * C_];         // [proj][m][k]
__device__ __align__(16) bf16 g_w_lo[3 * C_ * C_];
__device__ __align__(16) bf16 g_qt_hi[B_ * HEADS_ * N_ * DH_];  // [bh][n][d]
__device__ __align__(16) bf16 g_qt_lo[B_ * HEADS_ * N_ * DH_];
__device__ __align__(16) bf16 g_kt_hi[B_ * HEADS_ * N_ * DH_];
__device__ __align__(16) bf16 g_kt_lo[B_ * HEADS_ * N_ * DH_];
__device__ __align__(16) bf16 g_v_hi[B_ * HEADS_ * DH_ * N_];   // [bh][d][n]
__device__ __align__(16) bf16 g_v_lo[B_ * HEADS_ * DH_ * N_];
__device__ __align__(16) bf16 g_p_hi[HEADS_ * N_ * DH_];        // [h][n][d]
__device__ __align__(16) bf16 g_p_lo[HEADS_ * N_ * DH_];

// ------------------------------ prep ---------------------------------------
__global__ __launch_bounds__(256) void tsplit_kernel(const float* __restrict__ x,
                                                     const float* __restrict__ dt) {
    int z = blockIdx.z, b = z & 7, src = z >> 3;
    const float* X = (src ? dt : x) + (size_t)b * C_ * N_;
    __shared__ float t[32][33];
    int c0 = blockIdx.x * 32, n0 = blockIdx.y * 32;
    int tx = threadIdx.x & 31, ty = threadIdx.x >> 5;
#pragma unroll
    for (int i = 0; i < 4; i++) t[ty + i * 8][tx] = X[(size_t)(c0 + ty + i * 8) * N_ + n0 + tx];
    __syncthreads();
    bf16* dh = g_xt_hi + ((size_t)z * N_ + n0) * C_ + c0;
    bf16* dl = g_xt_lo + ((size_t)z * N_ + n0) * C_ + c0;
#pragma unroll
    for (int i = 0; i < 4; i++) {
        int n = ty + i * 8;
        float hi, lo;
        split2(t[tx][n], hi, lo);
        dh[(size_t)n * C_ + tx] = __float2bfloat16(hi);
        dl[(size_t)n * C_ + tx] = __float2bfloat16(lo);
    }
}
__global__ __launch_bounds__(256) void wsplit_kernel(const float* __restrict__ Wq,
                                                     const float* __restrict__ Wk,
                                                     const float* __restrict__ Wv) {
    int idx = blockIdx.x * 256 + threadIdx.x;
    if (idx >= 3 * C_ * C_) return;
    int p = idx / (C_ * C_);
    float v = (p == 0 ? Wq : p == 1 ? Wk : Wv)[idx - p * C_ * C_];
    float hi, lo;
    split2(v, hi, lo);
    g_w_hi[idx] = __float2bfloat16(hi);
    g_w_lo[idx] = __float2bfloat16(lo);
}
__global__ __launch_bounds__(256) void psplit_kernel(const float* __restrict__ rel_h,
                                                     const float* __restrict__ rel_w) {
    int idx = blockIdx.x * 256 + threadIdx.x;  // [h][n][d]
    if (idx >= HEADS_ * N_ * DH_) return;
    int d = idx & 63, n = (idx >> 6) & 1023, h = idx >> 16;
    float v = rel_h[(h * DH_ + d) * 32 + (n & 31)] + rel_w[(h * DH_ + d) * 32 + (n >> 5)];
    float hi, lo;
    split2(v, hi, lo);
    g_p_hi[idx] = __float2bfloat16(hi);
    g_p_lo[idx] = __float2bfloat16(lo);
}

// --------- generic mma.sync GEMM core, 3-stage cp.async pipeline -----------
// stage s: A @ s*36864 (128 rows x 144B), B @ +18432.
template <int NCH, typename F>
__device__ __forceinline__ void gemm_mma(char* smem, int tid, float acc[2][8][4], F fetch) {
    const int lane = tid & 31, wid = tid >> 5;
    const int wm0 = (wid & 3) * 32, wn0 = (wid >> 2) * 64;
    const uint32_t sb = smem_u32(smem);
    auto issue = [&](int c) {
        const bf16 *pa, *pb;
        int sa, sbs;
        fetch(c, pa, sa, pb, sbs);
        uint32_t da = sb + (c % 3) * 36864, db = da + 18432;
#pragma unroll
        for (int i = 0; i < 4; i++) {
            int s = tid + i * 256, r = s >> 3, seg = s & 7;
            CP16(da + r * 144 + seg * 16, pa + (size_t)r * sa + seg * 8);
            CP16(db + r * 144 + seg * 16, pb + (size_t)r * sbs + seg * 8);
        }
        CP_COMMIT();
    };
    issue(0);
    issue(1);
    for (int c = 0; c < NCH; c++) {
        if (c + 2 < NCH) { issue(c + 2); CP_WAIT(2); }
        else if (c + 1 < NCH) { CP_WAIT(1); }
        else { CP_WAIT(0); }
        __syncthreads();
        uint32_t da = sb + (c % 3) * 36864, db = da + 18432;
#pragma unroll
        for (int ks = 0; ks < 4; ks++) {
            uint32_t a[2][4], b[8][2];
#pragma unroll
            for (int mt = 0; mt < 2; mt++)
                ldm4(a[mt], da + (wm0 + mt * 16 + (lane & 15)) * 144 + ks * 32 + ((lane >> 4) << 4));
#pragma unroll
            for (int np = 0; np < 4; np++) {
                uint32_t r4[4];
                ldm4(r4, db + (wn0 + np * 16 + (lane & 7) + ((lane >> 4) << 3)) * 144 +
                             ks * 32 + (((lane >> 3) & 1) << 4));
                b[2 * np][0] = r4[0]; b[2 * np][1] = r4[1];
                b[2 * np + 1][0] = r4[2]; b[2 * np + 1][1] = r4[3];
            }
#pragma unroll
            for (int mt = 0; mt < 2; mt++)
#pragma unroll
                for (int nt = 0; nt < 8; nt++) mma16816(acc[mt][nt], a[mt], b[nt]);
        }
        __syncthreads();
    }
}

// ---------------- merged projections (q,k: z<16; v: z>=16) -----------------
__global__ __launch_bounds__(256, 1) void proj_kernel(const float* __restrict__ bq,
                                                      const float* __restrict__ bk,
                                                      const float* __restrict__ bv) {
    extern __shared__ char smem[];
    const int tid = threadIdx.x, z = blockIdx.z;
    const int m0 = blockIdx.x * 128, n0 = blockIdx.y * 128;
    const int lane = tid & 31, wid = tid >> 5;
    const int wm0 = (wid & 3) * 32, wn0 = (wid >> 2) * 64;
    float acc[2][8][4] = {};
    if (z < 16) {
        const int proj = z >> 3, b = z & 7;
        gemm_mma<24>(smem, tid, acc, [&](int c, const bf16*& pa, int& sa, const bf16*& pb, int& sbs) {
            int kb = c & 7, p = c >> 3;
            pa = (p == 2 ? g_xt_lo : g_xt_hi) + ((size_t)z * N_ + n0) * C_ + kb * 64;
            pb = (p == 1 ? g_w_lo : g_w_hi) + ((size_t)proj * C_ + m0) * C_ + kb * 64;
            sa = C_; sbs = C_;
        });
        const float* bias = proj ? bk : bq;
        bf16* dsth = proj ? g_kt_hi : g_qt_hi;
        bf16* dstl = proj ? g_kt_lo : g_qt_lo;
#pragma unroll
        for (int mt = 0; mt < 2; mt++)
#pragma unroll
            for (int rp = 0; rp < 2; rp++) {
                int n = n0 + wm0 + mt * 16 + (lane >> 2) + rp * 8;
#pragma unroll
                for (int nt = 0; nt < 8; nt++) {
                    int cc = m0 + wn0 + nt * 8 + (lane & 3) * 2;
                    float h0, l0, h1, l1;
                    split2(acc[mt][nt][2 * rp] + bias[cc], h0, l0);
                    split2(acc[mt][nt][2 * rp + 1] + bias[cc + 1], h1, l1);
                    size_t base = (((size_t)(b * 8 + (cc >> 6))) * N_ + n) * DH_ + (cc & 63);
                    *(uint32_t*)(dsth + base) = pack2(h0, h1);
                    *(uint32_t*)(dstl + base) = pack2(l0, l1);
                }
            }
    } else {
        const int b = z - 16;
        gemm_mma<24>(smem, tid, acc, [&](int c, const bf16*& pa, int& sa, const bf16*& pb, int& sbs) {
            int kb = c & 7, p = c >> 3;
            pa = (p == 2 ? g_w_lo : g_w_hi) + ((size_t)2 * C_ + m0) * C_ + kb * 64;
            pb = (p == 1 ? g_xt_lo : g_xt_hi) + ((size_t)(8 + b) * N_ + n0) * C_ + kb * 64;
            sa = C_; sbs = C_;
        });
#pragma unroll
        for (int mt = 0; mt < 2; mt++)
#pragma unroll
            for (int rp = 0; rp < 2; rp++) {
                int cc = m0 + wm0 + mt * 16 + (lane >> 2) + rp * 8;
                float bb = bv[cc];
                size_t rbase = ((size_t)b * 8 + (cc >> 6)) * DH_ * N_ + (size_t)(cc & 63) * N_;
#pragma unroll
                for (int nt = 0; nt < 8; nt++) {
                    int n = n0 + wn0 + nt * 8 + (lane & 3) * 2;
                    float h0, l0, h1, l1;
                    split2(acc[mt][nt][2 * rp] + bb, h0, l0);
                    split2(acc[mt][nt][2 * rp + 1] + bb, h1, l1);
                    *(uint32_t*)(g_v_hi + rbase + n) = pack2(h0, h1);
                    *(uint32_t*)(g_v_lo + rbase + n) = pack2(l0, l1);
                }
            }
    }
}

// ---------------- fused flash attention (logits + softmax + PV) ------------
// grid (8 i-tiles, 64 bh), 256 threads. 8 warps x (16 i-rows each, all cols).
// smem: A tiles Qh@0 Ql@18432 Ph@36864 Pl@55296 (128x144 each);
//       B double-buf @73728 + buf*55296: Kh@0 Kl@9216 Qjh@18432 Qjl@27648
//       Vh@36864 Vl@46080 (64x144 each). Total 184320.
__global__ __launch_bounds__(256, 1) void attn_kernel(float* __restrict__ out) {
    extern __shared__ char smem[];
    const int tid = threadIdx.x, lane = tid & 31, wid = tid >> 5;
    const int bh = blockIdx.y, h = bh & 7;
    const int i0 = blockIdx.x * 128;
    const uint32_t sb = smem_u32(smem);
    const uint32_t OF_B = 73728, BUFSZ = 55296;
    {   // A tiles (loaded once): Q_i, P_i hi/lo
        const bf16* s0 = g_qt_hi + ((size_t)bh * N_ + i0) * DH_;
        const bf16* s1 = g_qt_lo + ((size_t)bh * N_ + i0) * DH_;
        const bf16* s2 = g_p_hi + ((size_t)h * N_ + i0) * DH_;
        const bf16* s3 = g_p_lo + ((size_t)h * N_ + i0) * DH_;
#pragma unroll
        for (int i = 0; i < 4; i++) {
            int s = tid + i * 256, r = s >> 3, seg = s & 7;
            uint32_t d = (uint32_t)(r * 144 + seg * 16);
            CP16(sb + d, s0 + r * 64 + seg * 8);
            CP16(sb + 18432 + d, s1 + r * 64 + seg * 8);
            CP16(sb + 36864 + d, s2 + r * 64 + seg * 8);
            CP16(sb + 55296 + d, s3 + r * 64 + seg * 8);
        }
        CP_COMMIT();
    }
    const bf16* kh = g_kt_hi + (size_t)bh * N_ * DH_;
    const bf16* kl = g_kt_lo + (size_t)bh * N_ * DH_;
    const bf16* qjh = g_qt_hi + (size_t)bh * N_ * DH_;
    const bf16* qjl = g_qt_lo + (size_t)bh * N_ * DH_;
    const bf16* vh = g_v_hi + (size_t)bh * DH_ * N_;
    const bf16* vl = g_v_lo + (size_t)bh * DH_ * N_;
    auto issueB = [&](int j) {
        uint32_t base = sb + OF_B + (j & 1) * BUFSZ;
        int j0 = j * 64;
#pragma unroll
        for (int i = 0; i < 2; i++) {
            int s = tid + i * 256, r = s >> 3, seg = s & 7;
            uint32_t d = (uint32_t)(r * 144 + seg * 16);
            size_t sjd = (size_t)(j0 + r) * DH_ + seg * 8;   // [j][d]
            size_t sdj = (size_t)r * N_ + j0 + seg * 8;      // [d][j]
            CP16(base + d, kh + sjd);
            CP16(base + 9216 + d, kl + sjd);
            CP16(base + 18432 + d, qjh + sjd);
            CP16(base + 27648 + d, qjl + sjd);
            CP16(base + 36864 + d, vh + sdj);
            CP16(base + 46080 + d, vl + sdj);
        }
        CP_COMMIT();
    };
    issueB(0);
    float acco[8][4] = {};
    float mrow[2] = {-1e30f, -1e30f};
    float lrow[2] = {0.f, 0.f};
    const uint32_t arow = (uint32_t)((wid * 16 + (lane & 15)) * 144 + ((lane >> 4) << 4));
    const uint32_t brow = (uint32_t)(((lane & 7) + ((lane >> 4) << 3)) * 144 + (((lane >> 3) & 1) << 4));
    for (int j = 0; j < 16; j++) {
        if (j + 1 < 16) { issueB(j + 1); CP_WAIT(1); } else { CP_WAIT(0); }
        __syncthreads();
        uint32_t base = sb + OF_B + (j & 1) * BUFSZ;
        float accs[8][4] = {};
#pragma unroll
        for (int ks = 0; ks < 4; ks++) {
            uint32_t acol = ks * 32;
            uint32_t aQh[4], aQl[4], aPh[4], aPl[4];
            ldm4(aQh, sb + arow + acol);
            ldm4(aQl, sb + 18432 + arow + acol);
            ldm4(aPh, sb + 36864 + arow + acol);
            ldm4(aPl, sb + 55296 + arow + acol);
#pragma unroll
            for (int np = 0; np < 4; np++) {
                uint32_t roff = np * 2304 + brow + acol;
                uint32_t r4[4], b0[2], b1[2];
                ldm4(r4, base + roff);                 // K hi
                b0[0] = r4[0]; b0[1] = r4[1]; b1[0] = r4[2]; b1[1] = r4[3];
                mma16816(accs[2 * np], aQh, b0); mma16816(accs[2 * np + 1], aQh, b1);
                mma16816(accs[2 * np], aQl, b0); mma16816(accs[2 * np + 1], aQl, b1);
                ldm4(r4, base + 9216 + roff);          // K lo
                b0[0] = r4[0]; b0[1] = r4[1]; b1[0] = r4[2]; b1[1] = r4[3];
                mma16816(accs[2 * np], aQh, b0); mma16816(accs[2 * np + 1], aQh, b1);
                ldm4(r4, base + 18432 + roff);         // Qj hi
                b0[0] = r4[0]; b0[1] = r4[1]; b1[0] = r4[2]; b1[1] = r4[3];
                mma16816(accs[2 * np], aPh, b0); mma16816(accs[2 * np + 1], aPh, b1);
                mma16816(accs[2 * np], aPl, b0); mma16816(accs[2 * np + 1], aPl, b1);
                ldm4(r4, base + 27648 + roff);         // Qj lo
                b0[0] = r4[0]; b0[1] = r4[1]; b1[0] = r4[2]; b1[1] = r4[3];
                mma16816(accs[2 * np], aPh, b0); mma16816(accs[2 * np + 1], aPh, b1);
            }
        }
        // ---- online softmax (each row fully inside one warp quad) ----
        float mx[2] = {-1e30f, -1e30f};
#pragma unroll
        for (int nt = 0; nt < 8; nt++) {
            mx[0] = fmaxf(mx[0], fmaxf(accs[nt][0], accs[nt][1]));
            mx[1] = fmaxf(mx[1], fmaxf(accs[nt][2], accs[nt][3]));
        }
        float al[2], rs[2] = {0.f, 0.f};
#pragma unroll
        for (int q = 0; q < 2; q++) {
            mx[q] = fmaxf(mx[q], __shfl_xor_sync(~0u, mx[q], 1));
            mx[q] = fmaxf(mx[q], __shfl_xor_sync(~0u, mx[q], 2));
            float mn = fmaxf(mrow[q], mx[q]);
            al[q] = __expf(mrow[q] - mn);
            mrow[q] = mn;
        }
#pragma unroll
        for (int nt = 0; nt < 8; nt++) {
#pragma unroll
            for (int q = 0; q < 2; q++) {
                float p0 = __expf(accs[nt][2 * q] - mrow[q]);
                float p1 = __expf(accs[nt][2 * q + 1] - mrow[q]);
                accs[nt][2 * q] = p0;
                accs[nt][2 * q + 1] = p1;
                rs[q] += p0 + p1;
            }
        }
#pragma unroll
        for (int q = 0; q < 2; q++) {
            rs[q] += __shfl_xor_sync(~0u, rs[q], 1);
            rs[q] += __shfl_xor_sync(~0u, rs[q], 2);
            lrow[q] = lrow[q] * al[q] + rs[q];
        }
#pragma unroll
        for (int nt = 0; nt < 8; nt++) {
            acco[nt][0] *= al[0]; acco[nt][1] *= al[0];
            acco[nt][2] *= al[1]; acco[nt][3] *= al[1];
        }
        // ---- PV: P frags straight from registers (C-frag == A-frag layout) ----
#pragma unroll
        for (int ks = 0; ks < 4; ks++) {
            float* c0 = accs[2 * ks];
            float* c1 = accs[2 * ks + 1];
            uint32_t ph[4], pl[4];
            float h0, l0, h1, l1, h2, l2, h3, l3;
            split2(c0[0], h0, l0); split2(c0[1], h1, l1);
            split2(c0[2], h2, l2); split2(c0[3], h3, l3);
            ph[0] = pack2(h0, h1); ph[1] = pack2(h2, h3);
            pl[0] = pack2(l0, l1); pl[1] = pack2(l2, l3);
            split2(c1[0], h0, l0); split2(c1[1], h1, l1);
            split2(c1[2], h2, l2); split2(c1[3], h3, l3);
            ph[2] = pack2(h0, h1); ph[3] = pack2(h2, h3);
            pl[2] = pack2(l0, l1); pl[3] = pack2(l2, l3);
            uint32_t acol = ks * 32;
#pragma unroll
            for (int np = 0; np < 4; np++) {
                uint32_t roff = np * 2304 + brow + acol;
                uint32_t r4[4], b0[2], b1[2];
                ldm4(r4, base + 36864 + roff);         // V hi
                b0[0] = r4[0]; b0[1] = r4[1]; b1[0] = r4[2]; b1[1] = r4[3];
                mma16816(acco[2 * np], ph, b0); mma16816(acco[2 * np + 1], ph, b1);
                mma16816(acco[2 * np], pl, b0); mma16816(acco[2 * np + 1], pl, b1);
                ldm4(r4, base + 46080 + roff);         // V lo
                b0[0] = r4[0]; b0[1] = r4[1]; b1[0] = r4[2]; b1[1] = r4[3];
                mma16816(acco[2 * np], ph, b0); mma16816(acco[2 * np + 1], ph, b1);
            }
        }
        __syncthreads();
    }
    // ---- epilogue: divide by l, transpose via smem, write [bh][d][i] ----
    float inv[2] = {1.f / lrow[0], 1.f / lrow[1]};
    float* tr = (float*)smem;  // [64][132]
#pragma unroll
    for (int nt = 0; nt < 8; nt++) {
        int d = nt * 8 + (lane & 3) * 2;
        int r = wid * 16 + (lane >> 2);
        tr[d * 132 + r] = acco[nt][0] * inv[0];
        tr[(d + 1) * 132 + r] = acco[nt][1] * inv[0];
        tr[d * 132 + r + 8] = acco[nt][2] * inv[1];
        tr[(d + 1) * 132 + r + 8] = acco[nt][3] * inv[1];
    }
    __syncthreads();
    float* O = out + (size_t)bh * DH_ * N_;
#pragma unroll
    for (int i = 0; i < 8; i++) {
        int s = tid + i * 256, d = s >> 5, seg = s & 31;
        float4 v = make_float4(tr[d * 132 + seg * 4], tr[d * 132 + seg * 4 + 1],
                               tr[d * 132 + seg * 4 + 2], tr[d * 132 + seg * 4 + 3]);
        *(float4*)(O + (size_t)d * N_ + i0 + seg * 4) = v;
    }
}

// ------------------------------ launch -------------------------------------
extern "C" void kernel_launch(void* const* d_in, const int* in_sizes, int n_in,
                              void* d_out, int out_size) {
    const float* x = (const float*)d_in[0];
    const float* dtn = (const float*)d_in[1];
    const float* Wq = (const float*)d_in[2];
    const float* bq = (const float*)d_in[3];
    const float* Wk = (const float*)d_in[4];
    const float* bk = (const float*)d_in[5];
    const float* Wv = (const float*)d_in[6];
    const float* bv = (const float*)d_in[7];
    const float* rel_h = (const float*)d_in[8];
    const float* rel_w = (const float*)d_in[9];
    float* out = (float*)d_out;

    const int SM_GEMM = 110592, SM_ATT = 184320;
    static int once = 0;
    if (!once) {
        once = 1;
        cudaFuncSetAttribute(proj_kernel, cudaFuncAttributeMaxDynamicSharedMemorySize, SM_GEMM);
        cudaFuncSetAttribute(attn_kernel, cudaFuncAttributeMaxDynamicSharedMemorySize, SM_ATT);
    }

    tsplit_kernel<<<dim3(C_ / 32, N_ / 32, 16), 256>>>(x, dtn);
    wsplit_kernel<<<(3 * C_ * C_ + 255) / 256, 256>>>(Wq, Wk, Wv);
    psplit_kernel<<<(HEADS_ * N_ * DH_ + 255) / 256, 256>>>(rel_h, rel_w);
    proj_kernel<<<dim3(C_ / 128, N_ / 128, 24), 256, SM_GEMM>>>(bq, bk, bv);
    attn_kernel<<<dim3(N_ / 128, B_ * HEADS_), 256, SM_ATT>>>(out);
}

// round 6
// speedup vs baseline: 2.8781x; 1.1047x over previous
#include <cuda_runtime.h>
#include <cuda_bf16.h>
#include <cstdint>

#define B_ 8
#define C_ 512
#define N_ 1024
#define HEADS_ 8
#define DH_ 64
using bf16 = __nv_bfloat16;

// ------------------------------ helpers ------------------------------------
__device__ __forceinline__ uint32_t smem_u32(const void* p) {
    uint32_t a;
    asm("{ .reg .u64 t; cvta.to.shared.u64 t, %1; cvt.u32.u64 %0, t; }" : "=r"(a) : "l"(p));
    return a;
}
#define CP16(dst, src) asm volatile("cp.async.cg.shared.global [%0], [%1], 16;" :: "r"(dst), "l"(src) : "memory")
#define CP_COMMIT() asm volatile("cp.async.commit_group;" ::: "memory")
#define CP_WAIT(n) asm volatile("cp.async.wait_group %0;" :: "n"(n) : "memory")

__device__ __forceinline__ void ldm4(uint32_t (&r)[4], uint32_t addr) {
    asm volatile("ldmatrix.sync.aligned.m8n8.x4.shared.b16 {%0,%1,%2,%3}, [%4];"
                 : "=r"(r[0]), "=r"(r[1]), "=r"(r[2]), "=r"(r[3]) : "r"(addr));
}
__device__ __forceinline__ void mma16816(float (&d)[4], const uint32_t (&a)[4],
                                         const uint32_t (&b)[2]) {
    asm volatile("mma.sync.aligned.m16n8k16.row.col.f32.bf16.bf16.f32 "
                 "{%0,%1,%2,%3},{%4,%5,%6,%7},{%8,%9},{%0,%1,%2,%3};"
                 : "+f"(d[0]), "+f"(d[1]), "+f"(d[2]), "+f"(d[3])
                 : "r"(a[0]), "r"(a[1]), "r"(a[2]), "r"(a[3]), "r"(b[0]), "r"(b[1]));
}
__device__ __forceinline__ uint32_t pack2(float a, float b) {
    __nv_bfloat162 t = __floats2bfloat162_rn(a, b);
    return *(uint32_t*)&t;
}
__device__ __forceinline__ void split2(float v, float& hi, float& lo) {
    hi = __bfloat162float(__float2bfloat16(v));
    lo = v - hi;
}

// ------------------------------ scratch ------------------------------------
__device__ __align__(16) bf16 g_xt_hi[2 * B_ * N_ * C_];   // [src*8+b][n][c]
__device__ __align__(16) bf16 g_xt_lo[2 * B_ * N_ * C_];
__device__ __align__(16) bf16 g_w_hi[3 * C_ * C_];         // [proj][m][k]
__device__ __align__(16) bf16 g_w_lo[3 * C_ * C_];
__device__ __align__(16) bf16 g_qt_hi[B_ * HEADS_ * N_ * DH_];  // [bh][n][d]
__device__ __align__(16) bf16 g_qt_lo[B_ * HEADS_ * N_ * DH_];
__device__ __align__(16) bf16 g_kt_hi[B_ * HEADS_ * N_ * DH_];
__device__ __align__(16) bf16 g_kt_lo[B_ * HEADS_ * N_ * DH_];
__device__ __align__(16) bf16 g_v_hi[B_ * HEADS_ * DH_ * N_];   // [bh][d][n]
__device__ __align__(16) bf16 g_v_lo[B_ * HEADS_ * DH_ * N_];
__device__ __align__(16) bf16 g_p_hi[HEADS_ * N_ * DH_];        // [h][n][d]
__device__ __align__(16) bf16 g_p_lo[HEADS_ * N_ * DH_];

// ------------------------------ prep ---------------------------------------
__global__ __launch_bounds__(256) void tsplit_kernel(const float* __restrict__ x,
                                                     const float* __restrict__ dt) {
    int z = blockIdx.z, b = z & 7, src = z >> 3;
    const float* X = (src ? dt : x) + (size_t)b * C_ * N_;
    __shared__ float t[32][33];
    int c0 = blockIdx.x * 32, n0 = blockIdx.y * 32;
    int tx = threadIdx.x & 31, ty = threadIdx.x >> 5;
#pragma unroll
    for (int i = 0; i < 4; i++) t[ty + i * 8][tx] = X[(size_t)(c0 + ty + i * 8) * N_ + n0 + tx];
    __syncthreads();
    bf16* dh = g_xt_hi + ((size_t)z * N_ + n0) * C_ + c0;
    bf16* dl = g_xt_lo + ((size_t)z * N_ + n0) * C_ + c0;
#pragma unroll
    for (int i = 0; i < 4; i++) {
        int n = ty + i * 8;
        float hi, lo;
        split2(t[tx][n], hi, lo);
        dh[(size_t)n * C_ + tx] = __float2bfloat16(hi);
        dl[(size_t)n * C_ + tx] = __float2bfloat16(lo);
    }
}
__global__ __launch_bounds__(256) void wsplit_kernel(const float* __restrict__ Wq,
                                                     const float* __restrict__ Wk,
                                                     const float* __restrict__ Wv) {
    int idx = blockIdx.x * 256 + threadIdx.x;
    if (idx >= 3 * C_ * C_) return;
    int p = idx / (C_ * C_);
    float v = (p == 0 ? Wq : p == 1 ? Wk : Wv)[idx - p * C_ * C_];
    float hi, lo;
    split2(v, hi, lo);
    g_w_hi[idx] = __float2bfloat16(hi);
    g_w_lo[idx] = __float2bfloat16(lo);
}
__global__ __launch_bounds__(256) void psplit_kernel(const float* __restrict__ rel_h,
                                                     const float* __restrict__ rel_w) {
    int idx = blockIdx.x * 256 + threadIdx.x;  // [h][n][d]
    if (idx >= HEADS_ * N_ * DH_) return;
    int d = idx & 63, n = (idx >> 6) & 1023, h = idx >> 16;
    float v = rel_h[(h * DH_ + d) * 32 + (n & 31)] + rel_w[(h * DH_ + d) * 32 + (n >> 5)];
    float hi, lo;
    split2(v, hi, lo);
    g_p_hi[idx] = __float2bfloat16(hi);
    g_p_lo[idx] = __float2bfloat16(lo);
}

// ---- 3-term fused GEMM core: per chunk load Ahi/Alo/Bhi/Blo, 3 MMA passes --
// stage s @ s*73728: Ahi@0 Alo@18432 Bhi@36864 Blo@55296 (128 rows x 144B ea)
template <int NCH, typename F>
__device__ __forceinline__ void gemm3_mma(char* smem, int tid, float acc[2][8][4], F fetch) {
    const int lane = tid & 31, wid = tid >> 5;
    const int wm0 = (wid & 3) * 32, wn0 = (wid >> 2) * 64;
    const uint32_t sb = smem_u32(smem);
    auto issue = [&](int c) {
        const bf16 *pah, *pal, *pbh, *pbl;
        int sa, sbs;
        fetch(c, pah, pal, pbh, pbl, sa, sbs);
        uint32_t base = sb + (c & 1) * 73728;
#pragma unroll
        for (int i = 0; i < 4; i++) {
            int s = tid + i * 256, r = s >> 3, seg = s & 7;
            uint32_t d = (uint32_t)(r * 144 + seg * 16);
            CP16(base + d, pah + (size_t)r * sa + seg * 8);
            CP16(base + 18432 + d, pal + (size_t)r * sa + seg * 8);
            CP16(base + 36864 + d, pbh + (size_t)r * sbs + seg * 8);
            CP16(base + 55296 + d, pbl + (size_t)r * sbs + seg * 8);
        }
        CP_COMMIT();
    };
    issue(0);
    for (int c = 0; c < NCH; c++) {
        if (c + 1 < NCH) { issue(c + 1); CP_WAIT(1); } else { CP_WAIT(0); }
        __syncthreads();
        uint32_t base = sb + (c & 1) * 73728;
#pragma unroll
        for (int ks = 0; ks < 4; ks++) {
            uint32_t aH[2][4], aL[2][4], bH[8][2], bL[8][2];
#pragma unroll
            for (int mt = 0; mt < 2; mt++) {
                uint32_t roff = (wm0 + mt * 16 + (lane & 15)) * 144 + ks * 32 + ((lane >> 4) << 4);
                ldm4(aH[mt], base + roff);
                ldm4(aL[mt], base + 18432 + roff);
            }
#pragma unroll
            for (int np = 0; np < 4; np++) {
                uint32_t roff = (wn0 + np * 16 + (lane & 7) + ((lane >> 4) << 3)) * 144 +
                                ks * 32 + (((lane >> 3) & 1) << 4);
                uint32_t r4[4];
                ldm4(r4, base + 36864 + roff);
                bH[2 * np][0] = r4[0]; bH[2 * np][1] = r4[1];
                bH[2 * np + 1][0] = r4[2]; bH[2 * np + 1][1] = r4[3];
                ldm4(r4, base + 55296 + roff);
                bL[2 * np][0] = r4[0]; bL[2 * np][1] = r4[1];
                bL[2 * np + 1][0] = r4[2]; bL[2 * np + 1][1] = r4[3];
            }
#pragma unroll
            for (int mt = 0; mt < 2; mt++)
#pragma unroll
                for (int nt = 0; nt < 8; nt++) {
                    mma16816(acc[mt][nt], aH[mt], bH[nt]);
                    mma16816(acc[mt][nt], aH[mt], bL[nt]);
                    mma16816(acc[mt][nt], aL[mt], bH[nt]);
                }
        }
        __syncthreads();
    }
}

// ---------------- merged projections (q,k: z<16; v: z>=16) -----------------
__global__ __launch_bounds__(256, 1) void proj_kernel(const float* __restrict__ bq,
                                                      const float* __restrict__ bk,
                                                      const float* __restrict__ bv) {
    extern __shared__ char smem[];
    const int tid = threadIdx.x, z = blockIdx.z;
    const int m0 = blockIdx.x * 128, n0 = blockIdx.y * 128;
    const int lane = tid & 31, wid = tid >> 5;
    const int wm0 = (wid & 3) * 32, wn0 = (wid >> 2) * 64;
    float acc[2][8][4] = {};
    if (z < 16) {
        const int proj = z >> 3, b = z & 7;
        gemm3_mma<8>(smem, tid, acc, [&](int c, const bf16*& pah, const bf16*& pal,
                                         const bf16*& pbh, const bf16*& pbl, int& sa, int& sbs) {
            size_t ao = ((size_t)z * N_ + n0) * C_ + c * 64;
            size_t bo = ((size_t)proj * C_ + m0) * C_ + c * 64;
            pah = g_xt_hi + ao; pal = g_xt_lo + ao;
            pbh = g_w_hi + bo;  pbl = g_w_lo + bo;
            sa = C_; sbs = C_;
        });
        const float* bias = proj ? bk : bq;
        bf16* dsth = proj ? g_kt_hi : g_qt_hi;
        bf16* dstl = proj ? g_kt_lo : g_qt_lo;
#pragma unroll
        for (int mt = 0; mt < 2; mt++)
#pragma unroll
            for (int rp = 0; rp < 2; rp++) {
                int n = n0 + wm0 + mt * 16 + (lane >> 2) + rp * 8;
#pragma unroll
                for (int nt = 0; nt < 8; nt++) {
                    int cc = m0 + wn0 + nt * 8 + (lane & 3) * 2;
                    float h0, l0, h1, l1;
                    split2(acc[mt][nt][2 * rp] + bias[cc], h0, l0);
                    split2(acc[mt][nt][2 * rp + 1] + bias[cc + 1], h1, l1);
                    size_t base = (((size_t)(b * 8 + (cc >> 6))) * N_ + n) * DH_ + (cc & 63);
                    *(uint32_t*)(dsth + base) = pack2(h0, h1);
                    *(uint32_t*)(dstl + base) = pack2(l0, l1);
                }
            }
    } else {
        const int b = z - 16;
        gemm3_mma<8>(smem, tid, acc, [&](int c, const bf16*& pah, const bf16*& pal,
                                         const bf16*& pbh, const bf16*& pbl, int& sa, int& sbs) {
            size_t ao = ((size_t)2 * C_ + m0) * C_ + c * 64;
            size_t bo = ((size_t)(8 + b) * N_ + n0) * C_ + c * 64;
            pah = g_w_hi + ao;  pal = g_w_lo + ao;
            pbh = g_xt_hi + bo; pbl = g_xt_lo + bo;
            sa = C_; sbs = C_;
        });
#pragma unroll
        for (int mt = 0; mt < 2; mt++)
#pragma unroll
            for (int rp = 0; rp < 2; rp++) {
                int cc = m0 + wm0 + mt * 16 + (lane >> 2) + rp * 8;
                float bb = bv[cc];
                size_t rbase = ((size_t)b * 8 + (cc >> 6)) * DH_ * N_ + (size_t)(cc & 63) * N_;
#pragma unroll
                for (int nt = 0; nt < 8; nt++) {
                    int n = n0 + wn0 + nt * 8 + (lane & 3) * 2;
                    float h0, l0, h1, l1;
                    split2(acc[mt][nt][2 * rp] + bb, h0, l0);
                    split2(acc[mt][nt][2 * rp + 1] + bb, h1, l1);
                    *(uint32_t*)(g_v_hi + rbase + n) = pack2(h0, h1);
                    *(uint32_t*)(g_v_lo + rbase + n) = pack2(l0, l1);
                }
            }
    }
}

// ---------------- fused flash attention (logits + softmax + PV) ------------
// grid (8 i-tiles, 64 bh), 256 threads.
// smem: A tiles Qh@0 Ql@18432 Ph@36864 Pl@55296 (128x144 each);
//       B double-buf @73728 + buf*55296: Kh@0 Kl@9216 Qjh@18432 Qjl@27648
//       Vh@36864 Vl@46080 (64x144 each). Total 184320.
__global__ __launch_bounds__(256, 1) void attn_kernel(float* __restrict__ out) {
    extern __shared__ char smem[];
    const int tid = threadIdx.x, lane = tid & 31, wid = tid >> 5;
    const int bh = blockIdx.y, h = bh & 7;
    const int i0 = blockIdx.x * 128;
    const uint32_t sb = smem_u32(smem);
    const uint32_t OF_B = 73728, BUFSZ = 55296;
    {
        const bf16* s0 = g_qt_hi + ((size_t)bh * N_ + i0) * DH_;
        const bf16* s1 = g_qt_lo + ((size_t)bh * N_ + i0) * DH_;
        const bf16* s2 = g_p_hi + ((size_t)h * N_ + i0) * DH_;
        const bf16* s3 = g_p_lo + ((size_t)h * N_ + i0) * DH_;
#pragma unroll
        for (int i = 0; i < 4; i++) {
            int s = tid + i * 256, r = s >> 3, seg = s & 7;
            uint32_t d = (uint32_t)(r * 144 + seg * 16);
            CP16(sb + d, s0 + r * 64 + seg * 8);
            CP16(sb + 18432 + d, s1 + r * 64 + seg * 8);
            CP16(sb + 36864 + d, s2 + r * 64 + seg * 8);
            CP16(sb + 55296 + d, s3 + r * 64 + seg * 8);
        }
        CP_COMMIT();
    }
    const bf16* kh = g_kt_hi + (size_t)bh * N_ * DH_;
    const bf16* kl = g_kt_lo + (size_t)bh * N_ * DH_;
    const bf16* qjh = g_qt_hi + (size_t)bh * N_ * DH_;
    const bf16* qjl = g_qt_lo + (size_t)bh * N_ * DH_;
    const bf16* vh = g_v_hi + (size_t)bh * DH_ * N_;
    const bf16* vl = g_v_lo + (size_t)bh * DH_ * N_;
    auto issueB = [&](int j) {
        uint32_t base = sb + OF_B + (j & 1) * BUFSZ;
        int j0 = j * 64;
#pragma unroll
        for (int i = 0; i < 2; i++) {
            int s = tid + i * 256, r = s >> 3, seg = s & 7;
            uint32_t d = (uint32_t)(r * 144 + seg * 16);
            size_t sjd = (size_t)(j0 + r) * DH_ + seg * 8;
            size_t sdj = (size_t)r * N_ + j0 + seg * 8;
            CP16(base + d, kh + sjd);
            CP16(base + 9216 + d, kl + sjd);
            CP16(base + 18432 + d, qjh + sjd);
            CP16(base + 27648 + d, qjl + sjd);
            CP16(base + 36864 + d, vh + sdj);
            CP16(base + 46080 + d, vl + sdj);
        }
        CP_COMMIT();
    };
    issueB(0);
    float acco[8][4] = {};
    float mrow[2] = {-1e30f, -1e30f};
    float lrow[2] = {0.f, 0.f};
    const uint32_t arow = (uint32_t)((wid * 16 + (lane & 15)) * 144 + ((lane >> 4) << 4));
    const uint32_t brow = (uint32_t)(((lane & 7) + ((lane >> 4) << 3)) * 144 + (((lane >> 3) & 1) << 4));
    for (int j = 0; j < 16; j++) {
        if (j + 1 < 16) { issueB(j + 1); CP_WAIT(1); } else { CP_WAIT(0); }
        __syncthreads();
        uint32_t base = sb + OF_B + (j & 1) * BUFSZ;
        float accs[8][4] = {};
#pragma unroll
        for (int ks = 0; ks < 4; ks++) {
            uint32_t acol = ks * 32;
            uint32_t aQh[4], aQl[4], aPh[4], aPl[4];
            ldm4(aQh, sb + arow + acol);
            ldm4(aQl, sb + 18432 + arow + acol);
            ldm4(aPh, sb + 36864 + arow + acol);
            ldm4(aPl, sb + 55296 + arow + acol);
#pragma unroll
            for (int np = 0; np < 4; np++) {
                uint32_t roff = np * 2304 + brow + acol;
                uint32_t r4[4], b0[2], b1[2];
                ldm4(r4, base + roff);
                b0[0] = r4[0]; b0[1] = r4[1]; b1[0] = r4[2]; b1[1] = r4[3];
                mma16816(accs[2 * np], aQh, b0); mma16816(accs[2 * np + 1], aQh, b1);
                mma16816(accs[2 * np], aQl, b0); mma16816(accs[2 * np + 1], aQl, b1);
                ldm4(r4, base + 9216 + roff);
                b0[0] = r4[0]; b0[1] = r4[1]; b1[0] = r4[2]; b1[1] = r4[3];
                mma16816(accs[2 * np], aQh, b0); mma16816(accs[2 * np + 1], aQh, b1);
                ldm4(r4, base + 18432 + roff);
                b0[0] = r4[0]; b0[1] = r4[1]; b1[0] = r4[2]; b1[1] = r4[3];
                mma16816(accs[2 * np], aPh, b0); mma16816(accs[2 * np + 1], aPh, b1);
                mma16816(accs[2 * np], aPl, b0); mma16816(accs[2 * np + 1], aPl, b1);
                ldm4(r4, base + 27648 + roff);
                b0[0] = r4[0]; b0[1] = r4[1]; b1[0] = r4[2]; b1[1] = r4[3];
                mma16816(accs[2 * np], aPh, b0); mma16816(accs[2 * np + 1], aPh, b1);
            }
        }
        float mx[2] = {-1e30f, -1e30f};
#pragma unroll
        for (int nt = 0; nt < 8; nt++) {
            mx[0] = fmaxf(mx[0], fmaxf(accs[nt][0], accs[nt][1]));
            mx[1] = fmaxf(mx[1], fmaxf(accs[nt][2], accs[nt][3]));
        }
        float al[2], rs[2] = {0.f, 0.f};
#pragma unroll
        for (int q = 0; q < 2; q++) {
            mx[q] = fmaxf(mx[q], __shfl_xor_sync(~0u, mx[q], 1));
            mx[q] = fmaxf(mx[q], __shfl_xor_sync(~0u, mx[q], 2));
            float mn = fmaxf(mrow[q], mx[q]);
            al[q] = __expf(mrow[q] - mn);
            mrow[q] = mn;
        }
#pragma unroll
        for (int nt = 0; nt < 8; nt++) {
#pragma unroll
            for (int q = 0; q < 2; q++) {
                float p0 = __expf(accs[nt][2 * q] - mrow[q]);
                float p1 = __expf(accs[nt][2 * q + 1] - mrow[q]);
                accs[nt][2 * q] = p0;
                accs[nt][2 * q + 1] = p1;
                rs[q] += p0 + p1;
            }
        }
#pragma unroll
        for (int q = 0; q < 2; q++) {
            rs[q] += __shfl_xor_sync(~0u, rs[q], 1);
            rs[q] += __shfl_xor_sync(~0u, rs[q], 2);
            lrow[q] = lrow[q] * al[q] + rs[q];
        }
#pragma unroll
        for (int nt = 0; nt < 8; nt++) {
            acco[nt][0] *= al[0]; acco[nt][1] *= al[0];
            acco[nt][2] *= al[1]; acco[nt][3] *= al[1];
        }
#pragma unroll
        for (int ks = 0; ks < 4; ks++) {
            float* c0 = accs[2 * ks];
            float* c1 = accs[2 * ks + 1];
            uint32_t ph[4], pl[4];
            float h0, l0, h1, l1, h2, l2, h3, l3;
            split2(c0[0], h0, l0); split2(c0[1], h1, l1);
            split2(c0[2], h2, l2); split2(c0[3], h3, l3);
            ph[0] = pack2(h0, h1); ph[1] = pack2(h2, h3);
            pl[0] = pack2(l0, l1); pl[1] = pack2(l2, l3);
            split2(c1[0], h0, l0); split2(c1[1], h1, l1);
            split2(c1[2], h2, l2); split2(c1[3], h3, l3);
            ph[2] = pack2(h0, h1); ph[3] = pack2(h2, h3);
            pl[2] = pack2(l0, l1); pl[3] = pack2(l2, l3);
            uint32_t acol = ks * 32;
#pragma unroll
            for (int np = 0; np < 4; np++) {
                uint32_t roff = np * 2304 + brow + acol;
                uint32_t r4[4], b0[2], b1[2];
                ldm4(r4, base + 36864 + roff);
                b0[0] = r4[0]; b0[1] = r4[1]; b1[0] = r4[2]; b1[1] = r4[3];
                mma16816(acco[2 * np], ph, b0); mma16816(acco[2 * np + 1], ph, b1);
                mma16816(acco[2 * np], pl, b0); mma16816(acco[2 * np + 1], pl, b1);
                ldm4(r4, base + 46080 + roff);
                b0[0] = r4[0]; b0[1] = r4[1]; b1[0] = r4[2]; b1[1] = r4[3];
                mma16816(acco[2 * np], ph, b0); mma16816(acco[2 * np + 1], ph, b1);
            }
        }
        __syncthreads();
    }
    float inv[2] = {1.f / lrow[0], 1.f / lrow[1]};
    float* tr = (float*)smem;  // [64][132]
#pragma unroll
    for (int nt = 0; nt < 8; nt++) {
        int d = nt * 8 + (lane & 3) * 2;
        int r = wid * 16 + (lane >> 2);
        tr[d * 132 + r] = acco[nt][0] * inv[0];
        tr[(d + 1) * 132 + r] = acco[nt][1] * inv[0];
        tr[d * 132 + r + 8] = acco[nt][2] * inv[1];
        tr[(d + 1) * 132 + r + 8] = acco[nt][3] * inv[1];
    }
    __syncthreads();
    float* O = out + (size_t)bh * DH_ * N_;
#pragma unroll
    for (int i = 0; i < 8; i++) {
        int s = tid + i * 256, d = s >> 5, seg = s & 31;
        float4 v = make_float4(tr[d * 132 + seg * 4], tr[d * 132 + seg * 4 + 1],
                               tr[d * 132 + seg * 4 + 2], tr[d * 132 + seg * 4 + 3]);
        *(float4*)(O + (size_t)d * N_ + i0 + seg * 4) = v;
    }
}

// ------------------------------ launch -------------------------------------
extern "C" void kernel_launch(void* const* d_in, const int* in_sizes, int n_in,
                              void* d_out, int out_size) {
    const float* x = (const float*)d_in[0];
    const float* dtn = (const float*)d_in[1];
    const float* Wq = (const float*)d_in[2];
    const float* bq = (const float*)d_in[3];
    const float* Wk = (const float*)d_in[4];
    const float* bk = (const float*)d_in[5];
    const float* Wv = (const float*)d_in[6];
    const float* bv = (const float*)d_in[7];
    const float* rel_h = (const float*)d_in[8];
    const float* rel_w = (const float*)d_in[9];
    float* out = (float*)d_out;

    const int SM_GEMM = 147456, SM_ATT = 184320;
    static int once = 0;
    if (!once) {
        once = 1;
        cudaFuncSetAttribute(proj_kernel, cudaFuncAttributeMaxDynamicSharedMemorySize, SM_GEMM);
        cudaFuncSetAttribute(attn_kernel, cudaFuncAttributeMaxDynamicSharedMemorySize, SM_ATT);
    }

    tsplit_kernel<<<dim3(C_ / 32, N_ / 32, 16), 256>>>(x, dtn);
    wsplit_kernel<<<(3 * C_ * C_ + 255) / 256, 256>>>(Wq, Wk, Wv);
    psplit_kernel<<<(HEADS_ * N_ * DH_ + 255) / 256, 256>>>(rel_h, rel_w);
    proj_kernel<<<dim3(C_ / 128, N_ / 128, 24), 256, SM_GEMM>>>(bq, bk, bv);
    attn_kernel<<<dim3(N_ / 128, B_ * HEADS_), 256, SM_ATT>>>(out);
}

// round 7
// speedup vs baseline: 3.0743x; 1.0682x over previous
#include <cuda_runtime.h>
#include <cuda_bf16.h>
#include <cstdint>

#define B_ 8
#define C_ 512
#define N_ 1024
#define HEADS_ 8
#define DH_ 64
using bf16 = __nv_bfloat16;

// ------------------------------ helpers ------------------------------------
__device__ __forceinline__ uint32_t smem_u32(const void* p) {
    uint32_t a;
    asm("{ .reg .u64 t; cvta.to.shared.u64 t, %1; cvt.u32.u64 %0, t; }" : "=r"(a) : "l"(p));
    return a;
}
#define CP16(dst, src) asm volatile("cp.async.cg.shared.global [%0], [%1], 16;" :: "r"(dst), "l"(src) : "memory")
#define CP_COMMIT() asm volatile("cp.async.commit_group;" ::: "memory")
#define CP_WAIT(n) asm volatile("cp.async.wait_group %0;" :: "n"(n) : "memory")

__device__ __forceinline__ void ldm4(uint32_t (&r)[4], uint32_t addr) {
    asm volatile("ldmatrix.sync.aligned.m8n8.x4.shared.b16 {%0,%1,%2,%3}, [%4];"
                 : "=r"(r[0]), "=r"(r[1]), "=r"(r[2]), "=r"(r[3]) : "r"(addr));
}
__device__ __forceinline__ void mma16816(float (&d)[4], const uint32_t (&a)[4],
                                         const uint32_t (&b)[2]) {
    asm volatile("mma.sync.aligned.m16n8k16.row.col.f32.bf16.bf16.f32 "
                 "{%0,%1,%2,%3},{%4,%5,%6,%7},{%8,%9},{%0,%1,%2,%3};"
                 : "+f"(d[0]), "+f"(d[1]), "+f"(d[2]), "+f"(d[3])
                 : "r"(a[0]), "r"(a[1]), "r"(a[2]), "r"(a[3]), "r"(b[0]), "r"(b[1]));
}
__device__ __forceinline__ uint32_t pack2(float a, float b) {
    __nv_bfloat162 t = __floats2bfloat162_rn(a, b);
    return *(uint32_t*)&t;
}
__device__ __forceinline__ void split2(float v, float& hi, float& lo) {
    hi = __bfloat162float(__float2bfloat16(v));
    lo = v - hi;
}

// ------------------------------ scratch ------------------------------------
__device__ __align__(16) bf16 g_xt_hi[2 * B_ * N_ * C_];   // [src*8+b][n][c]
__device__ __align__(16) bf16 g_xt_lo[2 * B_ * N_ * C_];
__device__ __align__(16) bf16 g_w_hi[3 * C_ * C_];         // [proj][m][k]
__device__ __align__(16) bf16 g_w_lo[3 * C_ * C_];
__device__ __align__(16) bf16 g_qt_hi[B_ * HEADS_ * N_ * DH_];  // [bh][n][d]
__device__ __align__(16) bf16 g_qt_lo[B_ * HEADS_ * N_ * DH_];
__device__ __align__(16) bf16 g_kt_hi[B_ * HEADS_ * N_ * DH_];
__device__ __align__(16) bf16 g_kt_lo[B_ * HEADS_ * N_ * DH_];
__device__ __align__(16) bf16 g_v_hi[B_ * HEADS_ * DH_ * N_];   // [bh][d][n]
__device__ __align__(16) bf16 g_v_lo[B_ * HEADS_ * DH_ * N_];
__device__ __align__(16) bf16 g_p_hi[HEADS_ * N_ * DH_];        // [h][n][d]
__device__ __align__(16) bf16 g_p_lo[HEADS_ * N_ * DH_];

// ------------------------------ prep ---------------------------------------
__global__ __launch_bounds__(256) void tsplit_kernel(const float* __restrict__ x,
                                                     const float* __restrict__ dt) {
    int z = blockIdx.z, b = z & 7, src = z >> 3;
    const float* X = (src ? dt : x) + (size_t)b * C_ * N_;
    __shared__ float t[32][33];
    int c0 = blockIdx.x * 32, n0 = blockIdx.y * 32;
    int tx = threadIdx.x & 31, ty = threadIdx.x >> 5;
#pragma unroll
    for (int i = 0; i < 4; i++) t[ty + i * 8][tx] = X[(size_t)(c0 + ty + i * 8) * N_ + n0 + tx];
    __syncthreads();
    bf16* dh = g_xt_hi + ((size_t)z * N_ + n0) * C_ + c0;
    bf16* dl = g_xt_lo + ((size_t)z * N_ + n0) * C_ + c0;
#pragma unroll
    for (int i = 0; i < 4; i++) {
        int n = ty + i * 8;
        float hi, lo;
        split2(t[tx][n], hi, lo);
        dh[(size_t)n * C_ + tx] = __float2bfloat16(hi);
        dl[(size_t)n * C_ + tx] = __float2bfloat16(lo);
    }
}
__global__ __launch_bounds__(256) void wsplit_kernel(const float* __restrict__ Wq,
                                                     const float* __restrict__ Wk,
                                                     const float* __restrict__ Wv) {
    int idx = blockIdx.x * 256 + threadIdx.x;
    if (idx >= 3 * C_ * C_) return;
    int p = idx / (C_ * C_);
    float v = (p == 0 ? Wq : p == 1 ? Wk : Wv)[idx - p * C_ * C_];
    float hi, lo;
    split2(v, hi, lo);
    g_w_hi[idx] = __float2bfloat16(hi);
    g_w_lo[idx] = __float2bfloat16(lo);
}
__global__ __launch_bounds__(256) void psplit_kernel(const float* __restrict__ rel_h,
                                                     const float* __restrict__ rel_w) {
    int idx = blockIdx.x * 256 + threadIdx.x;  // [h][n][d]
    if (idx >= HEADS_ * N_ * DH_) return;
    int d = idx & 63, n = (idx >> 6) & 1023, h = idx >> 16;
    float v = rel_h[(h * DH_ + d) * 32 + (n & 31)] + rel_w[(h * DH_ + d) * 32 + (n >> 5)];
    float hi, lo;
    split2(v, hi, lo);
    g_p_hi[idx] = __float2bfloat16(hi);
    g_p_lo[idx] = __float2bfloat16(lo);
}

// ---- 3-term fused GEMM core, 128(A-rows) x 64(B-rows) tile, k-chunk 64 ----
// stage @ (c&1)*55296: Ahi@0(128x144) Alo@18432 Bhi@36864(64x144) Blo@46080
template <int NCH, typename F>
__device__ __forceinline__ void gemm3s(char* smem, int tid, float acc[2][4][4], F fetch) {
    const int lane = tid & 31, wid = tid >> 5;
    const int wm0 = (wid & 3) * 32, wn0 = (wid >> 2) * 32;
    const uint32_t sb = smem_u32(smem);
    auto issue = [&](int c) {
        const bf16 *pah, *pal, *pbh, *pbl;
        int sa, sbs;
        fetch(c, pah, pal, pbh, pbl, sa, sbs);
        uint32_t base = sb + (c & 1) * 55296;
#pragma unroll
        for (int i = 0; i < 4; i++) {
            int s = tid + i * 256, r = s >> 3, seg = s & 7;
            uint32_t d = (uint32_t)(r * 144 + seg * 16);
            CP16(base + d, pah + (size_t)r * sa + seg * 8);
            CP16(base + 18432 + d, pal + (size_t)r * sa + seg * 8);
        }
#pragma unroll
        for (int i = 0; i < 2; i++) {
            int s = tid + i * 256, r = s >> 3, seg = s & 7;
            uint32_t d = (uint32_t)(r * 144 + seg * 16);
            CP16(base + 36864 + d, pbh + (size_t)r * sbs + seg * 8);
            CP16(base + 46080 + d, pbl + (size_t)r * sbs + seg * 8);
        }
        CP_COMMIT();
    };
    issue(0);
    for (int c = 0; c < NCH; c++) {
        if (c + 1 < NCH) { issue(c + 1); CP_WAIT(1); } else { CP_WAIT(0); }
        __syncthreads();
        uint32_t base = sb + (c & 1) * 55296;
#pragma unroll
        for (int ks = 0; ks < 4; ks++) {
            uint32_t aH[2][4], aL[2][4], bH[4][2], bL[4][2];
#pragma unroll
            for (int mt = 0; mt < 2; mt++) {
                uint32_t roff = (wm0 + mt * 16 + (lane & 15)) * 144 + ks * 32 + ((lane >> 4) << 4);
                ldm4(aH[mt], base + roff);
                ldm4(aL[mt], base + 18432 + roff);
            }
#pragma unroll
            for (int np = 0; np < 2; np++) {
                uint32_t roff = (wn0 + np * 16 + (lane & 7) + ((lane >> 4) << 3)) * 144 +
                                ks * 32 + (((lane >> 3) & 1) << 4);
                uint32_t r4[4];
                ldm4(r4, base + 36864 + roff);
                bH[2 * np][0] = r4[0]; bH[2 * np][1] = r4[1];
                bH[2 * np + 1][0] = r4[2]; bH[2 * np + 1][1] = r4[3];
                ldm4(r4, base + 46080 + roff);
                bL[2 * np][0] = r4[0]; bL[2 * np][1] = r4[1];
                bL[2 * np + 1][0] = r4[2]; bL[2 * np + 1][1] = r4[3];
            }
#pragma unroll
            for (int mt = 0; mt < 2; mt++)
#pragma unroll
                for (int nt = 0; nt < 4; nt++) {
                    mma16816(acc[mt][nt], aH[mt], bH[nt]);
                    mma16816(acc[mt][nt], aH[mt], bL[nt]);
                    mma16816(acc[mt][nt], aL[mt], bH[nt]);
                }
        }
        __syncthreads();
    }
}

// ---------------- proj q/k: grid (m/64=8, n/128=8, 16) ---------------------
__global__ __launch_bounds__(256, 2) void proj_qk_kernel(const float* __restrict__ bq,
                                                         const float* __restrict__ bk) {
    extern __shared__ char smem[];
    const int tid = threadIdx.x, z = blockIdx.z, proj = z >> 3, b = z & 7;
    const int m0 = blockIdx.x * 64, n0 = blockIdx.y * 128;
    const int lane = tid & 31, wid = tid >> 5;
    const int wm0 = (wid & 3) * 32, wn0 = (wid >> 2) * 32;
    float acc[2][4][4] = {};
    gemm3s<8>(smem, tid, acc, [&](int c, const bf16*& pah, const bf16*& pal,
                                  const bf16*& pbh, const bf16*& pbl, int& sa, int& sbs) {
        size_t ao = ((size_t)z * N_ + n0) * C_ + c * 64;
        size_t bo = ((size_t)proj * C_ + m0) * C_ + c * 64;
        pah = g_xt_hi + ao; pal = g_xt_lo + ao;
        pbh = g_w_hi + bo;  pbl = g_w_lo + bo;
        sa = C_; sbs = C_;
    });
    const float* bias = proj ? bk : bq;
    bf16* dsth = proj ? g_kt_hi : g_qt_hi;
    bf16* dstl = proj ? g_kt_lo : g_qt_lo;
#pragma unroll
    for (int mt = 0; mt < 2; mt++)
#pragma unroll
        for (int rp = 0; rp < 2; rp++) {
            int n = n0 + wm0 + mt * 16 + (lane >> 2) + rp * 8;
#pragma unroll
            for (int nt = 0; nt < 4; nt++) {
                int cc = m0 + wn0 + nt * 8 + (lane & 3) * 2;
                float h0, l0, h1, l1;
                split2(acc[mt][nt][2 * rp] + bias[cc], h0, l0);
                split2(acc[mt][nt][2 * rp + 1] + bias[cc + 1], h1, l1);
                size_t base = (((size_t)(b * 8 + (cc >> 6))) * N_ + n) * DH_ + (cc & 63);
                *(uint32_t*)(dsth + base) = pack2(h0, h1);
                *(uint32_t*)(dstl + base) = pack2(l0, l1);
            }
        }
}

// ---------------- proj v: grid (n/64=16, m/128=4, 8) -----------------------
__global__ __launch_bounds__(256, 2) void proj_v_kernel(const float* __restrict__ bv) {
    extern __shared__ char smem[];
    const int tid = threadIdx.x, b = blockIdx.z;
    const int n0 = blockIdx.x * 64, m0 = blockIdx.y * 128;
    const int lane = tid & 31, wid = tid >> 5;
    const int wm0 = (wid & 3) * 32, wn0 = (wid >> 2) * 32;
    float acc[2][4][4] = {};
    gemm3s<8>(smem, tid, acc, [&](int c, const bf16*& pah, const bf16*& pal,
                                  const bf16*& pbh, const bf16*& pbl, int& sa, int& sbs) {
        size_t ao = ((size_t)2 * C_ + m0) * C_ + c * 64;
        size_t bo = ((size_t)(8 + b) * N_ + n0) * C_ + c * 64;
        pah = g_w_hi + ao;  pal = g_w_lo + ao;
        pbh = g_xt_hi + bo; pbl = g_xt_lo + bo;
        sa = C_; sbs = C_;
    });
#pragma unroll
    for (int mt = 0; mt < 2; mt++)
#pragma unroll
        for (int rp = 0; rp < 2; rp++) {
            int cc = m0 + wm0 + mt * 16 + (lane >> 2) + rp * 8;
            float bb = bv[cc];
            size_t rbase = ((size_t)b * 8 + (cc >> 6)) * DH_ * N_ + (size_t)(cc & 63) * N_;
#pragma unroll
            for (int nt = 0; nt < 4; nt++) {
                int n = n0 + wn0 + nt * 8 + (lane & 3) * 2;
                float h0, l0, h1, l1;
                split2(acc[mt][nt][2 * rp] + bb, h0, l0);
                split2(acc[mt][nt][2 * rp + 1] + bb, h1, l1);
                *(uint32_t*)(g_v_hi + rbase + n) = pack2(h0, h1);
                *(uint32_t*)(g_v_lo + rbase + n) = pack2(l0, l1);
            }
        }
}

// ---------------- fused flash attention, SW128 swizzled, 2 CTAs/SM ---------
// A tiles (128x128B swizzled): Qh@0 Ql@16384 Ph@32768 Pl@49152.
// B single-buffer @65536: Kh@+0 Kl@+8192 Qjh@+16384 Qjl@+24576 Vh@+32768
// Vl@+40960 (64x128B each). Total 114688.
__global__ __launch_bounds__(256, 2) void attn_kernel(float* __restrict__ out) {
    extern __shared__ char smem[];
    const int tid = threadIdx.x, lane = tid & 31, wid = tid >> 5;
    const int bh = blockIdx.y, h = bh & 7;
    const int i0 = blockIdx.x * 128;
    const uint32_t sb = smem_u32(smem);
    const uint32_t OFB = 65536;
    {   // A tiles, swizzled dst: off = r*128 + ((seg ^ (r&7))<<4)
        const bf16* s0 = g_qt_hi + ((size_t)bh * N_ + i0) * DH_;
        const bf16* s1 = g_qt_lo + ((size_t)bh * N_ + i0) * DH_;
        const bf16* s2 = g_p_hi + ((size_t)h * N_ + i0) * DH_;
        const bf16* s3 = g_p_lo + ((size_t)h * N_ + i0) * DH_;
#pragma unroll
        for (int i = 0; i < 4; i++) {
            int s = tid + i * 256, r = s >> 3, seg = s & 7;
            uint32_t d = (uint32_t)(r * 128 + ((seg ^ (r & 7)) << 4));
            CP16(sb + d, s0 + r * 64 + seg * 8);
            CP16(sb + 16384 + d, s1 + r * 64 + seg * 8);
            CP16(sb + 32768 + d, s2 + r * 64 + seg * 8);
            CP16(sb + 49152 + d, s3 + r * 64 + seg * 8);
        }
        CP_COMMIT();
    }
    const bf16* kh = g_kt_hi + (size_t)bh * N_ * DH_;
    const bf16* kl = g_kt_lo + (size_t)bh * N_ * DH_;
    const bf16* qjh = g_qt_hi + (size_t)bh * N_ * DH_;
    const bf16* qjl = g_qt_lo + (size_t)bh * N_ * DH_;
    const bf16* vh = g_v_hi + (size_t)bh * DH_ * N_;
    const bf16* vl = g_v_lo + (size_t)bh * DH_ * N_;
    float acco[8][4] = {};
    float mrow[2] = {-1e30f, -1e30f};
    float lrow[2] = {0.f, 0.f};
    const int ra = wid * 16 + (lane & 15), xa = ra & 7, ca = lane >> 4;
    const int rb = (lane & 7) + ((lane >> 4) << 3), xb = lane & 7, cb = (lane >> 3) & 1;
    for (int j = 0; j < 16; j++) {
        __syncthreads();   // prior iter's ldm4 of B done before overwrite
        {   // single-buffer B loads, swizzled
            int j0 = j * 64;
#pragma unroll
            for (int i = 0; i < 2; i++) {
                int s = tid + i * 256, r = s >> 3, seg = s & 7;
                uint32_t d = OFB + (uint32_t)(r * 128 + ((seg ^ (r & 7)) << 4));
                size_t sjd = (size_t)(j0 + r) * DH_ + seg * 8;
                size_t sdj = (size_t)r * N_ + j0 + seg * 8;
                CP16(sb + d, kh + sjd);
                CP16(sb + 8192 + d, kl + sjd);
                CP16(sb + 16384 + d, qjh + sjd);
                CP16(sb + 24576 + d, qjl + sjd);
                CP16(sb + 32768 + d, vh + sdj);
                CP16(sb + 40960 + d, vl + sdj);
            }
            CP_COMMIT();
        }
        CP_WAIT(0);
        __syncthreads();
        float accs[8][4] = {};
#pragma unroll
        for (int ks = 0; ks < 4; ks++) {
            uint32_t aoff = (uint32_t)(ra * 128 + ((((ks << 1) + ca) ^ xa) << 4));
            uint32_t aQh[4], aQl[4], aPh[4], aPl[4];
            ldm4(aQh, sb + aoff);
            ldm4(aQl, sb + 16384 + aoff);
            ldm4(aPh, sb + 32768 + aoff);
            ldm4(aPl, sb + 49152 + aoff);
            uint32_t boff0 = OFB + (uint32_t)(rb * 128 + ((((ks << 1) + cb) ^ xb) << 4));
#pragma unroll
            for (int np = 0; np < 4; np++) {
                uint32_t roff = boff0 + np * 2048;
                uint32_t r4[4], b0[2], b1[2];
                ldm4(r4, sb + roff);                   // K hi
                b0[0] = r4[0]; b0[1] = r4[1]; b1[0] = r4[2]; b1[1] = r4[3];
                mma16816(accs[2 * np], aQh, b0); mma16816(accs[2 * np + 1], aQh, b1);
                mma16816(accs[2 * np], aQl, b0); mma16816(accs[2 * np + 1], aQl, b1);
                ldm4(r4, sb + 8192 + roff);            // K lo
                b0[0] = r4[0]; b0[1] = r4[1]; b1[0] = r4[2]; b1[1] = r4[3];
                mma16816(accs[2 * np], aQh, b0); mma16816(accs[2 * np + 1], aQh, b1);
                ldm4(r4, sb + 16384 + roff);           // Qj hi
                b0[0] = r4[0]; b0[1] = r4[1]; b1[0] = r4[2]; b1[1] = r4[3];
                mma16816(accs[2 * np], aPh, b0); mma16816(accs[2 * np + 1], aPh, b1);
                mma16816(accs[2 * np], aPl, b0); mma16816(accs[2 * np + 1], aPl, b1);
                ldm4(r4, sb + 24576 + roff);           // Qj lo
                b0[0] = r4[0]; b0[1] = r4[1]; b1[0] = r4[2]; b1[1] = r4[3];
                mma16816(accs[2 * np], aPh, b0); mma16816(accs[2 * np + 1], aPh, b1);
            }
        }
        // ---- online softmax ----
        float mx[2] = {-1e30f, -1e30f};
#pragma unroll
        for (int nt = 0; nt < 8; nt++) {
            mx[0] = fmaxf(mx[0], fmaxf(accs[nt][0], accs[nt][1]));
            mx[1] = fmaxf(mx[1], fmaxf(accs[nt][2], accs[nt][3]));
        }
        float al[2], rs[2] = {0.f, 0.f};
#pragma unroll
        for (int q = 0; q < 2; q++) {
            mx[q] = fmaxf(mx[q], __shfl_xor_sync(~0u, mx[q], 1));
            mx[q] = fmaxf(mx[q], __shfl_xor_sync(~0u, mx[q], 2));
            float mn = fmaxf(mrow[q], mx[q]);
            al[q] = __expf(mrow[q] - mn);
            mrow[q] = mn;
        }
#pragma unroll
        for (int nt = 0; nt < 8; nt++) {
#pragma unroll
            for (int q = 0; q < 2; q++) {
                float p0 = __expf(accs[nt][2 * q] - mrow[q]);
                float p1 = __expf(accs[nt][2 * q + 1] - mrow[q]);
                accs[nt][2 * q] = p0;
                accs[nt][2 * q + 1] = p1;
                rs[q] += p0 + p1;
            }
        }
#pragma unroll
        for (int q = 0; q < 2; q++) {
            rs[q] += __shfl_xor_sync(~0u, rs[q], 1);
            rs[q] += __shfl_xor_sync(~0u, rs[q], 2);
            lrow[q] = lrow[q] * al[q] + rs[q];
        }
#pragma unroll
        for (int nt = 0; nt < 8; nt++) {
            acco[nt][0] *= al[0]; acco[nt][1] *= al[0];
            acco[nt][2] *= al[1]; acco[nt][3] *= al[1];
        }
        // ---- PV: P frags from registers ----
#pragma unroll
        for (int ks = 0; ks < 4; ks++) {
            float* c0 = accs[2 * ks];
            float* c1 = accs[2 * ks + 1];
            uint32_t ph[4], pl[4];
            float h0, l0, h1, l1, h2, l2, h3, l3;
            split2(c0[0], h0, l0); split2(c0[1], h1, l1);
            split2(c0[2], h2, l2); split2(c0[3], h3, l3);
            ph[0] = pack2(h0, h1); ph[1] = pack2(h2, h3);
            pl[0] = pack2(l0, l1); pl[1] = pack2(l2, l3);
            split2(c1[0], h0, l0); split2(c1[1], h1, l1);
            split2(c1[2], h2, l2); split2(c1[3], h3, l3);
            ph[2] = pack2(h0, h1); ph[3] = pack2(h2, h3);
            pl[2] = pack2(l0, l1); pl[3] = pack2(l2, l3);
            uint32_t boff0 = OFB + (uint32_t)(rb * 128 + ((((ks << 1) + cb) ^ xb) << 4));
#pragma unroll
            for (int np = 0; np < 4; np++) {
                uint32_t roff = boff0 + np * 2048;
                uint32_t r4[4], b0[2], b1[2];
                ldm4(r4, sb + 32768 + roff);           // V hi
                b0[0] = r4[0]; b0[1] = r4[1]; b1[0] = r4[2]; b1[1] = r4[3];
                mma16816(acco[2 * np], ph, b0); mma16816(acco[2 * np + 1], ph, b1);
                mma16816(acco[2 * np], pl, b0); mma16816(acco[2 * np + 1], pl, b1);
                ldm4(r4, sb + 40960 + roff);           // V lo
                b0[0] = r4[0]; b0[1] = r4[1]; b1[0] = r4[2]; b1[1] = r4[3];
                mma16816(acco[2 * np], ph, b0); mma16816(acco[2 * np + 1], ph, b1);
            }
        }
    }
    __syncthreads();
    // ---- epilogue: divide, transpose via smem, write [bh][d][i] ----
    float inv[2] = {1.f / lrow[0], 1.f / lrow[1]};
    float* tr = (float*)smem;  // [64][132]
#pragma unroll
    for (int nt = 0; nt < 8; nt++) {
        int d = nt * 8 + (lane & 3) * 2;
        int r = wid * 16 + (lane >> 2);
        tr[d * 132 + r] = acco[nt][0] * inv[0];
        tr[(d + 1) * 132 + r] = acco[nt][1] * inv[0];
        tr[d * 132 + r + 8] = acco[nt][2] * inv[1];
        tr[(d + 1) * 132 + r + 8] = acco[nt][3] * inv[1];
    }
    __syncthreads();
    float* O = out + (size_t)bh * DH_ * N_;
#pragma unroll
    for (int i = 0; i < 8; i++) {
        int s = tid + i * 256, d = s >> 5, seg = s & 31;
        float4 v = make_float4(tr[d * 132 + seg * 4], tr[d * 132 + seg * 4 + 1],
                               tr[d * 132 + seg * 4 + 2], tr[d * 132 + seg * 4 + 3]);
        *(float4*)(O + (size_t)d * N_ + i0 + seg * 4) = v;
    }
}

// ------------------------------ launch -------------------------------------
extern "C" void kernel_launch(void* const* d_in, const int* in_sizes, int n_in,
                              void* d_out, int out_size) {
    const float* x = (const float*)d_in[0];
    const float* dtn = (const float*)d_in[1];
    const float* Wq = (const float*)d_in[2];
    const float* bq = (const float*)d_in[3];
    const float* Wk = (const float*)d_in[4];
    const float* bk = (const float*)d_in[5];
    const float* Wv = (const float*)d_in[6];
    const float* bv = (const float*)d_in[7];
    const float* rel_h = (const float*)d_in[8];
    const float* rel_w = (const float*)d_in[9];
    float* out = (float*)d_out;

    const int SM_GEMM = 110592, SM_ATT = 114688;
    static int once = 0;
    if (!once) {
        once = 1;
        cudaFuncSetAttribute(proj_qk_kernel, cudaFuncAttributeMaxDynamicSharedMemorySize, SM_GEMM);
        cudaFuncSetAttribute(proj_v_kernel, cudaFuncAttributeMaxDynamicSharedMemorySize, SM_GEMM);
        cudaFuncSetAttribute(attn_kernel, cudaFuncAttributeMaxDynamicSharedMemorySize, SM_ATT);
    }

    tsplit_kernel<<<dim3(C_ / 32, N_ / 32, 16), 256>>>(x, dtn);
    wsplit_kernel<<<(3 * C_ * C_ + 255) / 256, 256>>>(Wq, Wk, Wv);
    psplit_kernel<<<(HEADS_ * N_ * DH_ + 255) / 256, 256>>>(rel_h, rel_w);
    proj_qk_kernel<<<dim3(C_ / 64, N_ / 128, 16), 256, SM_GEMM>>>(bq, bk);
    proj_v_kernel<<<dim3(N_ / 64, C_ / 128, B_), 256, SM_GEMM>>>(bv);
    attn_kernel<<<dim3(N_ / 128, B_ * HEADS_), 256, SM_ATT>>>(out);
}